// round 4
// baseline (speedup 1.0000x reference)
#include <cuda_runtime.h>
#include <cstdint>

#define N_NODES 100000
#define N_EDGES 1600000
#define DIN 48
#define DOUT 128
#define OUT_ELEMS (N_NODES * DOUT)                     // 12,800,000
#define FULL_OUT  (OUT_ELEMS + 3 * N_EDGES + N_NODES)  // 17,700,000

// Scratch node-feature buffers (19.2 MB each) — L2-resident working set.
__device__ float g_bufA[(size_t)N_NODES * DIN];
__device__ float g_bufB[(size_t)N_NODES * DIN];

// ---------------------------------------------------------------------------
// Vectorized global float4 reduction (sm_90+).
// ---------------------------------------------------------------------------
__device__ __forceinline__ void red_add_v4(float* addr, float x, float y, float z, float w)
{
    asm volatile("red.global.add.v4.f32 [%0], {%1, %2, %3, %4};"
                 :: "l"(addr), "f"(x), "f"(y), "f"(z), "f"(w) : "memory");
}

// ---------------------------------------------------------------------------
// tf32 helpers: hi/lo split for 3xTF32 error-compensated MMA.
// ---------------------------------------------------------------------------
__device__ __forceinline__ void split_tf32(float x, uint32_t& hi, uint32_t& lo)
{
    float h, l;
    asm("cvt.rna.tf32.f32 %0, %1;" : "=f"(h) : "f"(x));
    float r = x - h;
    asm("cvt.rna.tf32.f32 %0, %1;" : "=f"(l) : "f"(r));
    hi = __float_as_uint(h);
    lo = __float_as_uint(l);
}

__device__ __forceinline__ void mma_tf32(float d[4],
                                         uint32_t a0, uint32_t a1, uint32_t a2, uint32_t a3,
                                         uint32_t b0, uint32_t b1)
{
    asm volatile("mma.sync.aligned.m16n8k8.row.col.f32.tf32.tf32.f32 "
                 "{%0,%1,%2,%3}, {%4,%5,%6,%7}, {%8,%9}, {%0,%1,%2,%3};"
                 : "+f"(d[0]), "+f"(d[1]), "+f"(d[2]), "+f"(d[3])
                 : "r"(a0), "r"(a1), "r"(a2), "r"(a3), "r"(b0), "r"(b1));
}

// ---------------------------------------------------------------------------
// Zero scratch buffers; also echo df into the output tail (fused tail_copy part).
// ---------------------------------------------------------------------------
template <bool WRITE_TAIL>
__global__ void zero_bufs(const float* __restrict__ df, float* __restrict__ out)
{
    int i = blockIdx.x * blockDim.x + threadIdx.x;
    if (i < N_NODES * DIN / 4) {
        ((float4*)g_bufA)[i] = make_float4(0.f, 0.f, 0.f, 0.f);
        ((float4*)g_bufB)[i] = make_float4(0.f, 0.f, 0.f, 0.f);
    }
    if (WRITE_TAIL && i < N_NODES)
        out[OUT_ELEMS + 3 * N_EDGES + i] = __ldg(df + i);
}

// ---------------------------------------------------------------------------
// Message-passing scatter: dst[end[e]] += src[start[e]] * dfs[e] (* df[start[e]])
// 12 threads per edge, one float4 chunk each. WRITE_TAIL (pass 1 only) also
// echoes sn/en/dfs into the output tail using lanes q=0..2.
// ---------------------------------------------------------------------------
template <bool USE_DF, bool WRITE_TAIL>
__global__ void scatter_pass(const float* __restrict__ src, float* __restrict__ dst,
                             const int*  __restrict__ sn,  const int* __restrict__ en,
                             const float* __restrict__ dfs, const float* __restrict__ df,
                             float* __restrict__ out)
{
    int t = blockIdx.x * blockDim.x + threadIdx.x;
    if (t >= N_EDGES * 12) return;
    int e = t / 12;
    int q = t - e * 12;
    int s = __ldg(sn + e);
    int d = __ldg(en + e);
    float f = __ldg(dfs + e);
    if (WRITE_TAIL) {
        float* p = out + OUT_ELEMS;
        if (q == 0) p[e]               = (float)s;
        if (q == 1) p[N_EDGES + e]     = (float)d;
        if (q == 2) p[2 * N_EDGES + e] = f;
    }
    if (USE_DF) f *= __ldg(df + s);
    float4 v = __ldg((const float4*)(src + (size_t)s * DIN) + q);
    float* dp = dst + (size_t)d * DIN + q * 4;
    red_add_v4(dp, v.x * f, v.y * f, v.z * f, v.w * f);
}

// ---------------------------------------------------------------------------
// Fused MLP on tensor cores (tf32 mma.sync, 3xTF32 compensation):
//   out = relu((x*df) @ W1 + b1) @ W2 + b2
// Block = 256 threads / 8 warps / 128 nodes. Each warp owns 16 nodes through
// both stages (no block sync in the mainloop). Padded smem strides make all
// fragment LDS conflict-free: yt stride 52, ht stride 132, W stride 136.
// ---------------------------------------------------------------------------
#define MLP_TM 128
#define MLP_THREADS 256
#define W1_STRIDE 136
#define W2_STRIDE 136
#define YT_STRIDE 52
#define HT_STRIDE 132
// floats: W1s 48*136 | W2s 128*136 | b1s 128 | b2s 128 | yt 128*52 | ht 128*132
#define MLP_SMEM_FLOATS (48*W1_STRIDE + 128*W2_STRIDE + 128 + 128 + MLP_TM*YT_STRIDE + MLP_TM*HT_STRIDE)

__global__ void __launch_bounds__(MLP_THREADS, 1)
mlp_kernel(const float* __restrict__ x, const float* __restrict__ df,
           const float* __restrict__ W1, const float* __restrict__ b1,
           const float* __restrict__ W2, const float* __restrict__ b2,
           float* __restrict__ out)
{
    extern __shared__ float sm[];
    float* W1s = sm;                            // [48][136]
    float* W2s = W1s + 48 * W1_STRIDE;          // [128][136]
    float* b1s = W2s + 128 * W2_STRIDE;         // [128]
    float* b2s = b1s + 128;                     // [128]
    float* yt  = b2s + 128;                     // [128][52]
    float* ht  = yt + MLP_TM * YT_STRIDE;       // [128][132]

    int tid = threadIdx.x;

    // Stage weights into smem with padded strides.
    for (int i = tid; i < 48 * 128; i += MLP_THREADS) {
        int k = i >> 7, n = i & 127;
        W1s[k * W1_STRIDE + n] = __ldg(W1 + i);
    }
    for (int i = tid; i < 128 * 128; i += MLP_THREADS) {
        int k = i >> 7, n = i & 127;
        W2s[k * W2_STRIDE + n] = __ldg(W2 + i);
    }
    if (tid < 128) { b1s[tid] = __ldg(b1 + tid); b2s[tid] = __ldg(b2 + tid); }

    // Stage input tile (x * df folded), zero-pad past N_NODES.
    int node0 = blockIdx.x * MLP_TM;
    for (int i = tid; i < MLP_TM * 48; i += MLP_THREADS) {
        int r = i / 48;
        int n = node0 + r;
        yt[r * YT_STRIDE + (i - r * 48)] =
            (n < N_NODES) ? __ldg(x + (size_t)n * 48 + (i - r * 48)) * __ldg(df + n) : 0.f;
    }
    __syncthreads();

    int warp = tid >> 5;
    int lane = tid & 31;
    int r = lane >> 2;   // 0..7
    int c = lane & 3;    // 0..3

    float d[16][4];

    // ================= stage 1: H = relu(Y @ W1 + b1), K = 48 =================
    #pragma unroll
    for (int nt = 0; nt < 16; nt++) {
        d[nt][0] = b1s[nt * 8 + 2 * c];
        d[nt][1] = b1s[nt * 8 + 2 * c + 1];
        d[nt][2] = d[nt][0];
        d[nt][3] = d[nt][1];
    }
    {
        const float* yb = yt + warp * 16 * YT_STRIDE;
        #pragma unroll
        for (int ks = 0; ks < 6; ks++) {
            int k0 = ks * 8;
            uint32_t ah[4], al[4];
            split_tf32(yb[r * YT_STRIDE + k0 + c],           ah[0], al[0]);
            split_tf32(yb[(r + 8) * YT_STRIDE + k0 + c],     ah[1], al[1]);
            split_tf32(yb[r * YT_STRIDE + k0 + c + 4],       ah[2], al[2]);
            split_tf32(yb[(r + 8) * YT_STRIDE + k0 + c + 4], ah[3], al[3]);
            #pragma unroll
            for (int nt = 0; nt < 16; nt++) {
                uint32_t bh0, bl0, bh1, bl1;
                split_tf32(W1s[(k0 + c) * W1_STRIDE + nt * 8 + r],     bh0, bl0);
                split_tf32(W1s[(k0 + c + 4) * W1_STRIDE + nt * 8 + r], bh1, bl1);
                mma_tf32(d[nt], ah[0], ah[1], ah[2], ah[3], bh0, bh1);   // hi*hi
                mma_tf32(d[nt], al[0], al[1], al[2], al[3], bh0, bh1);   // lo*hi
                mma_tf32(d[nt], ah[0], ah[1], ah[2], ah[3], bl0, bl1);   // hi*lo
            }
        }
    }
    // relu + store H to smem (each warp writes only its own 16 rows)
    {
        float* hb = ht + warp * 16 * HT_STRIDE;
        #pragma unroll
        for (int nt = 0; nt < 16; nt++) {
            float2 lo = make_float2(fmaxf(d[nt][0], 0.f), fmaxf(d[nt][1], 0.f));
            float2 hi = make_float2(fmaxf(d[nt][2], 0.f), fmaxf(d[nt][3], 0.f));
            *(float2*)(hb + r * HT_STRIDE + nt * 8 + 2 * c)       = lo;
            *(float2*)(hb + (r + 8) * HT_STRIDE + nt * 8 + 2 * c) = hi;
        }
    }
    __syncwarp();

    // ================= stage 2: OUT = H @ W2 + b2, K = 128 =================
    #pragma unroll
    for (int nt = 0; nt < 16; nt++) {
        d[nt][0] = b2s[nt * 8 + 2 * c];
        d[nt][1] = b2s[nt * 8 + 2 * c + 1];
        d[nt][2] = d[nt][0];
        d[nt][3] = d[nt][1];
    }
    {
        const float* hb = ht + warp * 16 * HT_STRIDE;
        #pragma unroll
        for (int ks = 0; ks < 16; ks++) {
            int k0 = ks * 8;
            uint32_t ah[4], al[4];
            split_tf32(hb[r * HT_STRIDE + k0 + c],           ah[0], al[0]);
            split_tf32(hb[(r + 8) * HT_STRIDE + k0 + c],     ah[1], al[1]);
            split_tf32(hb[r * HT_STRIDE + k0 + c + 4],       ah[2], al[2]);
            split_tf32(hb[(r + 8) * HT_STRIDE + k0 + c + 4], ah[3], al[3]);
            #pragma unroll
            for (int nt = 0; nt < 16; nt++) {
                uint32_t bh0, bl0, bh1, bl1;
                split_tf32(W2s[(k0 + c) * W2_STRIDE + nt * 8 + r],     bh0, bl0);
                split_tf32(W2s[(k0 + c + 4) * W2_STRIDE + nt * 8 + r], bh1, bl1);
                mma_tf32(d[nt], ah[0], ah[1], ah[2], ah[3], bh0, bh1);
                mma_tf32(d[nt], al[0], al[1], al[2], al[3], bh0, bh1);
                mma_tf32(d[nt], ah[0], ah[1], ah[2], ah[3], bl0, bl1);
            }
        }
    }
    // Store to global
    {
        int row0 = node0 + warp * 16 + r;
        int row1 = row0 + 8;
        #pragma unroll
        for (int nt = 0; nt < 16; nt++) {
            if (row0 < N_NODES)
                *(float2*)(out + (size_t)row0 * 128 + nt * 8 + 2 * c) =
                    make_float2(d[nt][0], d[nt][1]);
            if (row1 < N_NODES)
                *(float2*)(out + (size_t)row1 * 128 + nt * 8 + 2 * c) =
                    make_float2(d[nt][2], d[nt][3]);
        }
    }
}

extern "C" void kernel_launch(void* const* d_in, const int* in_sizes, int n_in,
                              void* d_out, int out_size)
{
    const float* y   = (const float*)d_in[0];
    const int*   sn  = (const int*)  d_in[1];
    const int*   en  = (const int*)  d_in[2];
    const float* dfs = (const float*)d_in[3];
    const float* df  = (const float*)d_in[4];
    const float* W1  = (const float*)d_in[5];
    const float* b1  = (const float*)d_in[6];
    const float* W2  = (const float*)d_in[7];
    const float* b2  = (const float*)d_in[8];
    float* out = (float*)d_out;

    float *bufA, *bufB;
    cudaGetSymbolAddress((void**)&bufA, g_bufA);
    cudaGetSymbolAddress((void**)&bufB, g_bufB);

    cudaFuncSetAttribute(mlp_kernel, cudaFuncAttributeMaxDynamicSharedMemorySize,
                         MLP_SMEM_FLOATS * (int)sizeof(float));

    const int ZB = (N_NODES * DIN / 4 + 255) / 256;
    const int SB = (N_EDGES * 12 + 255) / 256;
    const bool tail = (out_size >= FULL_OUT);

    if (tail) {
        zero_bufs<true><<<ZB, 256>>>(df, out);
        scatter_pass<false, true><<<SB, 256>>>(y, bufA, sn, en, dfs, df, out);
    } else {
        zero_bufs<false><<<ZB, 256>>>(df, out);
        scatter_pass<false, false><<<SB, 256>>>(y, bufA, sn, en, dfs, df, out);
    }

    // pass 2: bufB = segsum(bufA[s] * df[s] * dfs[e])  (pass-1 df folded in)
    scatter_pass<true, false><<<SB, 256>>>(bufA, bufB, sn, en, dfs, df, out);

    // fused tensor-core MLP -> out (pass-2 df folded into the x load)
    mlp_kernel<<<(N_NODES + MLP_TM - 1) / MLP_TM, MLP_THREADS,
                 MLP_SMEM_FLOATS * sizeof(float)>>>(bufB, df, W1, b1, W2, b2, out);
}

// round 5
// speedup vs baseline: 1.0905x; 1.0905x over previous
#include <cuda_runtime.h>
#include <cstdint>

#define N_NODES 100000
#define N_EDGES 1600000
#define DIN 48
#define DOUT 128
#define OUT_ELEMS (N_NODES * DOUT)                     // 12,800,000
#define FULL_OUT  (OUT_ELEMS + 3 * N_EDGES + N_NODES)  // 17,700,000

// Scratch node-feature buffers (19.2 MB each) — L2-resident working set.
__device__ float g_bufA[(size_t)N_NODES * DIN];
__device__ float g_bufB[(size_t)N_NODES * DIN];

// Pre-split tf32 weights (hi/lo), produced once by split_weights kernel.
__device__ uint32_t g_W1h[48 * 128], g_W1l[48 * 128];
__device__ uint32_t g_W2h[128 * 128], g_W2l[128 * 128];

// ---------------------------------------------------------------------------
// Vectorized global float4 reduction (sm_90+).
// ---------------------------------------------------------------------------
__device__ __forceinline__ void red_add_v4(float* addr, float x, float y, float z, float w)
{
    asm volatile("red.global.add.v4.f32 [%0], {%1, %2, %3, %4};"
                 :: "l"(addr), "f"(x), "f"(y), "f"(z), "f"(w) : "memory");
}

// ---------------------------------------------------------------------------
// tf32 helpers: hi/lo split for 3xTF32 error-compensated MMA.
// ---------------------------------------------------------------------------
__device__ __forceinline__ void split_tf32(float x, uint32_t& hi, uint32_t& lo)
{
    float h, l;
    asm("cvt.rna.tf32.f32 %0, %1;" : "=f"(h) : "f"(x));
    float r = x - h;
    asm("cvt.rna.tf32.f32 %0, %1;" : "=f"(l) : "f"(r));
    hi = __float_as_uint(h);
    lo = __float_as_uint(l);
}

__device__ __forceinline__ void mma_tf32(float d[4],
                                         uint32_t a0, uint32_t a1, uint32_t a2, uint32_t a3,
                                         uint32_t b0, uint32_t b1)
{
    asm volatile("mma.sync.aligned.m16n8k8.row.col.f32.tf32.tf32.f32 "
                 "{%0,%1,%2,%3}, {%4,%5,%6,%7}, {%8,%9}, {%0,%1,%2,%3};"
                 : "+f"(d[0]), "+f"(d[1]), "+f"(d[2]), "+f"(d[3])
                 : "r"(a0), "r"(a1), "r"(a2), "r"(a3), "r"(b0), "r"(b1));
}

// ---------------------------------------------------------------------------
// One-time weight split (hi/lo tf32).
// ---------------------------------------------------------------------------
__global__ void split_weights(const float* __restrict__ W1, const float* __restrict__ W2)
{
    int i = blockIdx.x * blockDim.x + threadIdx.x;
    if (i < 48 * 128)  split_tf32(__ldg(W1 + i), g_W1h[i], g_W1l[i]);
    if (i < 128 * 128) split_tf32(__ldg(W2 + i), g_W2h[i], g_W2l[i]);
}

// ---------------------------------------------------------------------------
// Zero both scratch buffers (float4 vectorized).
// ---------------------------------------------------------------------------
__global__ void zero_bufs()
{
    int i = blockIdx.x * blockDim.x + threadIdx.x;
    if (i < N_NODES * DIN / 4) {
        ((float4*)g_bufA)[i] = make_float4(0.f, 0.f, 0.f, 0.f);
        ((float4*)g_bufB)[i] = make_float4(0.f, 0.f, 0.f, 0.f);
    }
}

// ---------------------------------------------------------------------------
// Message-passing scatter: dst[end[e]] += src[start[e]] * dfs[e] (* df[start[e]])
// 12 threads per edge, one float4 chunk each.
// ---------------------------------------------------------------------------
template <bool USE_DF>
__global__ void scatter_pass(const float* __restrict__ src, float* __restrict__ dst,
                             const int*  __restrict__ sn,  const int* __restrict__ en,
                             const float* __restrict__ dfs, const float* __restrict__ df)
{
    int t = blockIdx.x * blockDim.x + threadIdx.x;
    if (t >= N_EDGES * 12) return;
    int e = t / 12;
    int q = t - e * 12;
    int s = __ldg(sn + e);
    int d = __ldg(en + e);
    float f = __ldg(dfs + e);
    if (USE_DF) f *= __ldg(df + s);
    float4 v = __ldg((const float4*)(src + (size_t)s * DIN) + q);
    float* dp = dst + (size_t)d * DIN + q * 4;
    red_add_v4(dp, v.x * f, v.y * f, v.z * f, v.w * f);
}

// ---------------------------------------------------------------------------
// Fused MLP on tensor cores (tf32 mma.sync, 3xTF32 compensation):
//   out = relu((x*df) @ W1 + b1) @ W2 + b2
// Weights come pre-split (hi/lo) from global; B-fragment loads are bare LDS.
// Stage-1 accumulators are converted in-register (shfl) to stage-2 A
// fragments — no smem H tile, no block sync in the mainloop.
// ---------------------------------------------------------------------------
#define MLP_TM 128
#define MLP_THREADS 256
#define W_STRIDE 136
#define YT_STRIDE 52
// u32/floats: W1h,W1l 48*136*2 | W2h,W2l 128*136*2 | b1,b2 256 | yt 128*52
#define MLP_SMEM_WORDS (48*W_STRIDE*2 + 128*W_STRIDE*2 + 256 + MLP_TM*YT_STRIDE)

__global__ void __launch_bounds__(MLP_THREADS, 1)
mlp_kernel(const float* __restrict__ x, const float* __restrict__ df,
           const float* __restrict__ b1, const float* __restrict__ b2,
           float* __restrict__ out)
{
    extern __shared__ uint32_t smu[];
    uint32_t* W1hs = smu;                         // [48][136]
    uint32_t* W1ls = W1hs + 48 * W_STRIDE;
    uint32_t* W2hs = W1ls + 48 * W_STRIDE;        // [128][136]
    uint32_t* W2ls = W2hs + 128 * W_STRIDE;
    float*    b1s  = (float*)(W2ls + 128 * W_STRIDE);  // [128]
    float*    b2s  = b1s + 128;                   // [128]
    float*    yt   = b2s + 128;                   // [128][52]

    int tid = threadIdx.x;

    // Stage pre-split weights into smem with padded stride.
    for (int i = tid; i < 48 * 128; i += MLP_THREADS) {
        int k = i >> 7, n = i & 127;
        W1hs[k * W_STRIDE + n] = g_W1h[i];
        W1ls[k * W_STRIDE + n] = g_W1l[i];
    }
    for (int i = tid; i < 128 * 128; i += MLP_THREADS) {
        int k = i >> 7, n = i & 127;
        W2hs[k * W_STRIDE + n] = g_W2h[i];
        W2ls[k * W_STRIDE + n] = g_W2l[i];
    }
    if (tid < 128) { b1s[tid] = __ldg(b1 + tid); b2s[tid] = __ldg(b2 + tid); }

    // Stage input tile (x * df folded), zero-pad past N_NODES.
    int node0 = blockIdx.x * MLP_TM;
    for (int i = tid; i < MLP_TM * 48; i += MLP_THREADS) {
        int r = i / 48;
        int n = node0 + r;
        yt[r * YT_STRIDE + (i - r * 48)] =
            (n < N_NODES) ? __ldg(x + (size_t)n * 48 + (i - r * 48)) * __ldg(df + n) : 0.f;
    }
    __syncthreads();

    int warp = tid >> 5;
    int lane = tid & 31;
    int r = lane >> 2;   // 0..7
    int c = lane & 3;    // 0..3

    float d[16][4];
    float h[16][4];

    // ================= stage 1: H = relu(Y @ W1 + b1), K = 48 =================
    #pragma unroll
    for (int nt = 0; nt < 16; nt++) {
        d[nt][0] = b1s[nt * 8 + 2 * c];
        d[nt][1] = b1s[nt * 8 + 2 * c + 1];
        d[nt][2] = d[nt][0];
        d[nt][3] = d[nt][1];
    }
    {
        const float* yb = yt + warp * 16 * YT_STRIDE;
        #pragma unroll
        for (int ks = 0; ks < 6; ks++) {
            int k0 = ks * 8;
            uint32_t ah[4], al[4];
            split_tf32(yb[r * YT_STRIDE + k0 + c],           ah[0], al[0]);
            split_tf32(yb[(r + 8) * YT_STRIDE + k0 + c],     ah[1], al[1]);
            split_tf32(yb[r * YT_STRIDE + k0 + c + 4],       ah[2], al[2]);
            split_tf32(yb[(r + 8) * YT_STRIDE + k0 + c + 4], ah[3], al[3]);
            #pragma unroll
            for (int nt = 0; nt < 16; nt++) {
                uint32_t bh0 = W1hs[(k0 + c) * W_STRIDE + nt * 8 + r];
                uint32_t bh1 = W1hs[(k0 + c + 4) * W_STRIDE + nt * 8 + r];
                uint32_t bl0 = W1ls[(k0 + c) * W_STRIDE + nt * 8 + r];
                uint32_t bl1 = W1ls[(k0 + c + 4) * W_STRIDE + nt * 8 + r];
                mma_tf32(d[nt], ah[0], ah[1], ah[2], ah[3], bh0, bh1);   // hi*hi
                mma_tf32(d[nt], al[0], al[1], al[2], al[3], bh0, bh1);   // lo*hi
                mma_tf32(d[nt], ah[0], ah[1], ah[2], ah[3], bl0, bl1);   // hi*lo
            }
        }
    }
    // relu into h (register-resident H tile)
    #pragma unroll
    for (int nt = 0; nt < 16; nt++) {
        h[nt][0] = fmaxf(d[nt][0], 0.f);
        h[nt][1] = fmaxf(d[nt][1], 0.f);
        h[nt][2] = fmaxf(d[nt][2], 0.f);
        h[nt][3] = fmaxf(d[nt][3], 0.f);
    }

    // ================= stage 2: OUT = H @ W2 + b2, K = 128 =================
    #pragma unroll
    for (int nt = 0; nt < 16; nt++) {
        d[nt][0] = b2s[nt * 8 + 2 * c];
        d[nt][1] = b2s[nt * 8 + 2 * c + 1];
        d[nt][2] = d[nt][0];
        d[nt][3] = d[nt][1];
    }
    {
        // C-layout -> A-layout conversion per k-step via shfl:
        // A[row][k0+j]: held as component (j&1) of lane (r*4 + (j>>1)).
        int srcA = (lane & ~3) | (c >> 1);
        int srcB = srcA + 2;
        bool odd = (c & 1);
        #pragma unroll
        for (int ks = 0; ks < 16; ks++) {
            int k0 = ks * 8;
            float w0 = __shfl_sync(0xFFFFFFFFu, h[ks][0], srcA);
            float w1 = __shfl_sync(0xFFFFFFFFu, h[ks][1], srcA);
            float w2 = __shfl_sync(0xFFFFFFFFu, h[ks][2], srcA);
            float w3 = __shfl_sync(0xFFFFFFFFu, h[ks][3], srcA);
            float x0 = __shfl_sync(0xFFFFFFFFu, h[ks][0], srcB);
            float x1 = __shfl_sync(0xFFFFFFFFu, h[ks][1], srcB);
            float x2 = __shfl_sync(0xFFFFFFFFu, h[ks][2], srcB);
            float x3 = __shfl_sync(0xFFFFFFFFu, h[ks][3], srcB);
            uint32_t ah[4], al[4];
            split_tf32(odd ? w1 : w0, ah[0], al[0]);   // A[r][k0+c]
            split_tf32(odd ? w3 : w2, ah[1], al[1]);   // A[r+8][k0+c]
            split_tf32(odd ? x1 : x0, ah[2], al[2]);   // A[r][k0+c+4]
            split_tf32(odd ? x3 : x2, ah[3], al[3]);   // A[r+8][k0+c+4]
            #pragma unroll
            for (int nt = 0; nt < 16; nt++) {
                uint32_t bh0 = W2hs[(k0 + c) * W_STRIDE + nt * 8 + r];
                uint32_t bh1 = W2hs[(k0 + c + 4) * W_STRIDE + nt * 8 + r];
                uint32_t bl0 = W2ls[(k0 + c) * W_STRIDE + nt * 8 + r];
                uint32_t bl1 = W2ls[(k0 + c + 4) * W_STRIDE + nt * 8 + r];
                mma_tf32(d[nt], ah[0], ah[1], ah[2], ah[3], bh0, bh1);
                mma_tf32(d[nt], al[0], al[1], al[2], al[3], bh0, bh1);
                mma_tf32(d[nt], ah[0], ah[1], ah[2], ah[3], bl0, bl1);
            }
        }
    }
    // Store to global
    {
        int row0 = node0 + warp * 16 + r;
        int row1 = row0 + 8;
        #pragma unroll
        for (int nt = 0; nt < 16; nt++) {
            if (row0 < N_NODES)
                *(float2*)(out + (size_t)row0 * 128 + nt * 8 + 2 * c) =
                    make_float2(d[nt][0], d[nt][1]);
            if (row1 < N_NODES)
                *(float2*)(out + (size_t)row1 * 128 + nt * 8 + 2 * c) =
                    make_float2(d[nt][2], d[nt][3]);
        }
    }
}

// ---------------------------------------------------------------------------
// Echo the passthrough outputs (ints value-cast to float, floats copied).
// ---------------------------------------------------------------------------
__global__ void tail_copy(float* __restrict__ out,
                          const int*  __restrict__ sn, const int* __restrict__ en,
                          const float* __restrict__ dfs, const float* __restrict__ df)
{
    int i = blockIdx.x * blockDim.x + threadIdx.x;
    float* p = out + OUT_ELEMS;
    if (i < N_EDGES) {
        p[i]               = (float)__ldg(sn + i);
        p[N_EDGES + i]     = (float)__ldg(en + i);
        p[2 * N_EDGES + i] = __ldg(dfs + i);
    }
    if (i < N_NODES)
        p[3 * N_EDGES + i] = __ldg(df + i);
}

extern "C" void kernel_launch(void* const* d_in, const int* in_sizes, int n_in,
                              void* d_out, int out_size)
{
    const float* y   = (const float*)d_in[0];
    const int*   sn  = (const int*)  d_in[1];
    const int*   en  = (const int*)  d_in[2];
    const float* dfs = (const float*)d_in[3];
    const float* df  = (const float*)d_in[4];
    const float* W1  = (const float*)d_in[5];
    const float* b1  = (const float*)d_in[6];
    const float* W2  = (const float*)d_in[7];
    const float* b2  = (const float*)d_in[8];
    float* out = (float*)d_out;

    float *bufA, *bufB;
    cudaGetSymbolAddress((void**)&bufA, g_bufA);
    cudaGetSymbolAddress((void**)&bufB, g_bufB);

    cudaFuncSetAttribute(mlp_kernel, cudaFuncAttributeMaxDynamicSharedMemorySize,
                         MLP_SMEM_WORDS * (int)sizeof(uint32_t));

    const int ZB = (N_NODES * DIN / 4 + 255) / 256;
    const int SB = (N_EDGES * 12 + 255) / 256;

    zero_bufs<<<ZB, 256>>>();
    split_weights<<<(128 * 128 + 255) / 256, 256>>>(W1, W2);

    // pass 1: bufA = segsum(y[s] * dfs[e])             (unscaled)
    scatter_pass<false><<<SB, 256>>>(y, bufA, sn, en, dfs, df);

    // pass 2: bufB = segsum(bufA[s] * df[s] * dfs[e])  (pass-1 df folded in)
    scatter_pass<true><<<SB, 256>>>(bufA, bufB, sn, en, dfs, df);

    // fused tensor-core MLP -> out (pass-2 df folded into the x load)
    mlp_kernel<<<(N_NODES + MLP_TM - 1) / MLP_TM, MLP_THREADS,
                 MLP_SMEM_WORDS * sizeof(uint32_t)>>>(bufB, df, b1, b2, out);

    // passthrough echoes, only if the output buffer holds the full tuple
    if (out_size >= FULL_OUT) {
        tail_copy<<<(N_EDGES + 255) / 256, 256>>>(out, sn, en, dfs, df);
    }
}

// round 6
// speedup vs baseline: 1.2947x; 1.1873x over previous
#include <cuda_runtime.h>
#include <cstdint>

#define N_NODES 100000
#define N_EDGES 1600000
#define DIN 48
#define DOUT 128
#define OUT_ELEMS (N_NODES * DOUT)                     // 12,800,000
#define FULL_OUT  (OUT_ELEMS + 3 * N_EDGES + N_NODES)  // 17,700,000

#define SCAN_BLOCKS ((N_NODES + 1023) / 1024)          // 98

// Scratch node-feature buffers (19.2 MB each) — written fully by gather, no zeroing.
__device__ float g_bufA[(size_t)N_NODES * DIN];
__device__ float g_bufB[(size_t)N_NODES * DIN];

// CSR-by-destination structures.
__device__ int    g_off[N_NODES + 1];      // counts -> exclusive offsets
__device__ int    g_cursor[N_NODES];       // fill cursors
__device__ int    g_bsum[SCAN_BLOCKS];     // per-block sums / prefixes
__device__ float2 g_epay[N_EDGES];         // {src_as_float_bits, dfs}

// Pre-split tf32 weights (hi/lo).
__device__ uint32_t g_W1h[48 * 128], g_W1l[48 * 128];
__device__ uint32_t g_W2h[128 * 128], g_W2l[128 * 128];

// ---------------------------------------------------------------------------
// tf32 helpers.
// ---------------------------------------------------------------------------
__device__ __forceinline__ void split_tf32(float x, uint32_t& hi, uint32_t& lo)
{
    float h, l;
    asm("cvt.rna.tf32.f32 %0, %1;" : "=f"(h) : "f"(x));
    float r = x - h;
    asm("cvt.rna.tf32.f32 %0, %1;" : "=f"(l) : "f"(r));
    hi = __float_as_uint(h);
    lo = __float_as_uint(l);
}

__device__ __forceinline__ void mma_tf32(float d[4],
                                         uint32_t a0, uint32_t a1, uint32_t a2, uint32_t a3,
                                         uint32_t b0, uint32_t b1)
{
    asm volatile("mma.sync.aligned.m16n8k8.row.col.f32.tf32.tf32.f32 "
                 "{%0,%1,%2,%3}, {%4,%5,%6,%7}, {%8,%9}, {%0,%1,%2,%3};"
                 : "+f"(d[0]), "+f"(d[1]), "+f"(d[2]), "+f"(d[3])
                 : "r"(a0), "r"(a1), "r"(a2), "r"(a3), "r"(b0), "r"(b1));
}

__global__ void split_weights(const float* __restrict__ W1, const float* __restrict__ W2)
{
    int i = blockIdx.x * blockDim.x + threadIdx.x;
    if (i < 48 * 128)  split_tf32(__ldg(W1 + i), g_W1h[i], g_W1l[i]);
    if (i < 128 * 128) split_tf32(__ldg(W2 + i), g_W2h[i], g_W2l[i]);
}

// ---------------------------------------------------------------------------
// CSR build: zero counts -> histogram -> 3-phase scan -> fill payloads.
// ---------------------------------------------------------------------------
__global__ void zero_counts()
{
    int i = blockIdx.x * blockDim.x + threadIdx.x;
    if (i < N_NODES) g_off[i] = 0;
}

__global__ void hist_kernel(const int* __restrict__ en)
{
    int e = blockIdx.x * blockDim.x + threadIdx.x;
    if (e < N_EDGES) atomicAdd(&g_off[__ldg(en + e)], 1);
}

// Phase A: per-block (1024-item) sums.
__global__ void scanA()
{
    __shared__ int sh[256];
    int tid = threadIdx.x;
    int base = blockIdx.x * 1024 + tid * 4;
    int s = 0;
    #pragma unroll
    for (int j = 0; j < 4; j++)
        s += (base + j < N_NODES) ? g_off[base + j] : 0;
    sh[tid] = s;
    __syncthreads();
    for (int d = 128; d > 0; d >>= 1) {
        if (tid < d) sh[tid] += sh[tid + d];
        __syncthreads();
    }
    if (tid == 0) g_bsum[blockIdx.x] = sh[0];
}

// Phase B: serial exclusive scan of block sums (tiny) + total sentinel.
__global__ void scanB()
{
    if (threadIdx.x == 0) {
        int run = 0;
        for (int i = 0; i < SCAN_BLOCKS; i++) {
            int v = g_bsum[i];
            g_bsum[i] = run;
            run += v;
        }
        g_off[N_NODES] = run;   // == N_EDGES
    }
}

// Phase C: block-local exclusive scan + block prefix; write offsets & cursors.
__global__ void scanC()
{
    __shared__ int sh[256];
    int tid = threadIdx.x;
    int base = blockIdx.x * 1024 + tid * 4;
    int v[4];
    int s = 0;
    #pragma unroll
    for (int j = 0; j < 4; j++) {
        v[j] = (base + j < N_NODES) ? g_off[base + j] : 0;
        s += v[j];
    }
    sh[tid] = s;
    __syncthreads();
    // Hillis-Steele inclusive scan over 256 thread sums.
    for (int d = 1; d < 256; d <<= 1) {
        int x = (tid >= d) ? sh[tid - d] : 0;
        __syncthreads();
        sh[tid] += x;
        __syncthreads();
    }
    int ex = sh[tid] - s + g_bsum[blockIdx.x];
    #pragma unroll
    for (int j = 0; j < 4; j++) {
        if (base + j < N_NODES) {
            g_off[base + j]    = ex;
            g_cursor[base + j] = ex;
        }
        ex += v[j];
    }
}

__global__ void fill_kernel(const int* __restrict__ sn, const int* __restrict__ en,
                            const float* __restrict__ dfs)
{
    int e = blockIdx.x * blockDim.x + threadIdx.x;
    if (e >= N_EDGES) return;
    int d = __ldg(en + e);
    int pos = atomicAdd(&g_cursor[d], 1);
    g_epay[pos] = make_float2(__int_as_float(__ldg(sn + e)), __ldg(dfs + e));
}

// ---------------------------------------------------------------------------
// Gather pass: dst[n] = df[n] * sum_{e: end=n} src[start_e] * dfs_e
// 12 threads per node, one float4 chunk each; edge payload broadcast across
// the 12-lane group. Unrolled by 2 for MLP.
// ---------------------------------------------------------------------------
__global__ void gather_pass(const float* __restrict__ src, float* __restrict__ dst,
                            const float* __restrict__ df)
{
    int t = blockIdx.x * blockDim.x + threadIdx.x;
    if (t >= N_NODES * 12) return;
    int n = t / 12;
    int q = t - n * 12;

    int o0 = __ldg(&g_off[n]);
    int o1 = __ldg(&g_off[n + 1]);

    float4 acc = make_float4(0.f, 0.f, 0.f, 0.f);
    int i = o0;
    for (; i + 2 <= o1; i += 2) {
        float2 p0 = __ldg(&g_epay[i]);
        float2 p1 = __ldg(&g_epay[i + 1]);
        int s0 = __float_as_int(p0.x);
        int s1 = __float_as_int(p1.x);
        float4 v0 = __ldg((const float4*)(src + (size_t)s0 * DIN) + q);
        float4 v1 = __ldg((const float4*)(src + (size_t)s1 * DIN) + q);
        acc.x = fmaf(v0.x, p0.y, acc.x); acc.y = fmaf(v0.y, p0.y, acc.y);
        acc.z = fmaf(v0.z, p0.y, acc.z); acc.w = fmaf(v0.w, p0.y, acc.w);
        acc.x = fmaf(v1.x, p1.y, acc.x); acc.y = fmaf(v1.y, p1.y, acc.y);
        acc.z = fmaf(v1.z, p1.y, acc.z); acc.w = fmaf(v1.w, p1.y, acc.w);
    }
    if (i < o1) {
        float2 p = __ldg(&g_epay[i]);
        int s = __float_as_int(p.x);
        float4 v = __ldg((const float4*)(src + (size_t)s * DIN) + q);
        acc.x = fmaf(v.x, p.y, acc.x); acc.y = fmaf(v.y, p.y, acc.y);
        acc.z = fmaf(v.z, p.y, acc.z); acc.w = fmaf(v.w, p.y, acc.w);
    }

    float f = __ldg(df + n);
    acc.x *= f; acc.y *= f; acc.z *= f; acc.w *= f;
    ((float4*)(dst + (size_t)n * DIN))[q] = acc;
}

// ---------------------------------------------------------------------------
// Fused MLP on tensor cores (tf32 mma.sync, 3xTF32 compensation):
//   out = relu(x @ W1 + b1) @ W2 + b2
// ---------------------------------------------------------------------------
#define MLP_TM 128
#define MLP_THREADS 256
#define W_STRIDE 136
#define YT_STRIDE 52
#define MLP_SMEM_WORDS (48*W_STRIDE*2 + 128*W_STRIDE*2 + 256 + MLP_TM*YT_STRIDE)

__global__ void __launch_bounds__(MLP_THREADS, 1)
mlp_kernel(const float* __restrict__ x,
           const float* __restrict__ b1, const float* __restrict__ b2,
           float* __restrict__ out)
{
    extern __shared__ uint32_t smu[];
    uint32_t* W1hs = smu;                         // [48][136]
    uint32_t* W1ls = W1hs + 48 * W_STRIDE;
    uint32_t* W2hs = W1ls + 48 * W_STRIDE;        // [128][136]
    uint32_t* W2ls = W2hs + 128 * W_STRIDE;
    float*    b1s  = (float*)(W2ls + 128 * W_STRIDE);
    float*    b2s  = b1s + 128;
    float*    yt   = b2s + 128;                   // [128][52]

    int tid = threadIdx.x;

    for (int i = tid; i < 48 * 128; i += MLP_THREADS) {
        int k = i >> 7, n = i & 127;
        W1hs[k * W_STRIDE + n] = g_W1h[i];
        W1ls[k * W_STRIDE + n] = g_W1l[i];
    }
    for (int i = tid; i < 128 * 128; i += MLP_THREADS) {
        int k = i >> 7, n = i & 127;
        W2hs[k * W_STRIDE + n] = g_W2h[i];
        W2ls[k * W_STRIDE + n] = g_W2l[i];
    }
    if (tid < 128) { b1s[tid] = __ldg(b1 + tid); b2s[tid] = __ldg(b2 + tid); }

    int node0 = blockIdx.x * MLP_TM;
    for (int i = tid; i < MLP_TM * 48; i += MLP_THREADS) {
        int r = i / 48;
        int n = node0 + r;
        yt[r * YT_STRIDE + (i - r * 48)] =
            (n < N_NODES) ? __ldg(x + (size_t)n * 48 + (i - r * 48)) : 0.f;
    }
    __syncthreads();

    int warp = tid >> 5;
    int lane = tid & 31;
    int r = lane >> 2;
    int c = lane & 3;

    float d[16][4];
    float h[16][4];

    // ---- stage 1: H = relu(Y @ W1 + b1), K = 48 ----
    #pragma unroll
    for (int nt = 0; nt < 16; nt++) {
        d[nt][0] = b1s[nt * 8 + 2 * c];
        d[nt][1] = b1s[nt * 8 + 2 * c + 1];
        d[nt][2] = d[nt][0];
        d[nt][3] = d[nt][1];
    }
    {
        const float* yb = yt + warp * 16 * YT_STRIDE;
        #pragma unroll
        for (int ks = 0; ks < 6; ks++) {
            int k0 = ks * 8;
            uint32_t ah[4], al[4];
            split_tf32(yb[r * YT_STRIDE + k0 + c],           ah[0], al[0]);
            split_tf32(yb[(r + 8) * YT_STRIDE + k0 + c],     ah[1], al[1]);
            split_tf32(yb[r * YT_STRIDE + k0 + c + 4],       ah[2], al[2]);
            split_tf32(yb[(r + 8) * YT_STRIDE + k0 + c + 4], ah[3], al[3]);
            #pragma unroll
            for (int nt = 0; nt < 16; nt++) {
                uint32_t bh0 = W1hs[(k0 + c) * W_STRIDE + nt * 8 + r];
                uint32_t bh1 = W1hs[(k0 + c + 4) * W_STRIDE + nt * 8 + r];
                uint32_t bl0 = W1ls[(k0 + c) * W_STRIDE + nt * 8 + r];
                uint32_t bl1 = W1ls[(k0 + c + 4) * W_STRIDE + nt * 8 + r];
                mma_tf32(d[nt], ah[0], ah[1], ah[2], ah[3], bh0, bh1);
                mma_tf32(d[nt], al[0], al[1], al[2], al[3], bh0, bh1);
                mma_tf32(d[nt], ah[0], ah[1], ah[2], ah[3], bl0, bl1);
            }
        }
    }
    #pragma unroll
    for (int nt = 0; nt < 16; nt++) {
        h[nt][0] = fmaxf(d[nt][0], 0.f);
        h[nt][1] = fmaxf(d[nt][1], 0.f);
        h[nt][2] = fmaxf(d[nt][2], 0.f);
        h[nt][3] = fmaxf(d[nt][3], 0.f);
    }

    // ---- stage 2: OUT = H @ W2 + b2, K = 128 ----
    #pragma unroll
    for (int nt = 0; nt < 16; nt++) {
        d[nt][0] = b2s[nt * 8 + 2 * c];
        d[nt][1] = b2s[nt * 8 + 2 * c + 1];
        d[nt][2] = d[nt][0];
        d[nt][3] = d[nt][1];
    }
    {
        int srcA = (lane & ~3) | (c >> 1);
        int srcB = srcA + 2;
        bool odd = (c & 1);
        #pragma unroll
        for (int ks = 0; ks < 16; ks++) {
            int k0 = ks * 8;
            float w0 = __shfl_sync(0xFFFFFFFFu, h[ks][0], srcA);
            float w1 = __shfl_sync(0xFFFFFFFFu, h[ks][1], srcA);
            float w2 = __shfl_sync(0xFFFFFFFFu, h[ks][2], srcA);
            float w3 = __shfl_sync(0xFFFFFFFFu, h[ks][3], srcA);
            float x0 = __shfl_sync(0xFFFFFFFFu, h[ks][0], srcB);
            float x1 = __shfl_sync(0xFFFFFFFFu, h[ks][1], srcB);
            float x2 = __shfl_sync(0xFFFFFFFFu, h[ks][2], srcB);
            float x3 = __shfl_sync(0xFFFFFFFFu, h[ks][3], srcB);
            uint32_t ah[4], al[4];
            split_tf32(odd ? w1 : w0, ah[0], al[0]);
            split_tf32(odd ? w3 : w2, ah[1], al[1]);
            split_tf32(odd ? x1 : x0, ah[2], al[2]);
            split_tf32(odd ? x3 : x2, ah[3], al[3]);
            #pragma unroll
            for (int nt = 0; nt < 16; nt++) {
                uint32_t bh0 = W2hs[(k0 + c) * W_STRIDE + nt * 8 + r];
                uint32_t bh1 = W2hs[(k0 + c + 4) * W_STRIDE + nt * 8 + r];
                uint32_t bl0 = W2ls[(k0 + c) * W_STRIDE + nt * 8 + r];
                uint32_t bl1 = W2ls[(k0 + c + 4) * W_STRIDE + nt * 8 + r];
                mma_tf32(d[nt], ah[0], ah[1], ah[2], ah[3], bh0, bh1);
                mma_tf32(d[nt], al[0], al[1], al[2], al[3], bh0, bh1);
                mma_tf32(d[nt], ah[0], ah[1], ah[2], ah[3], bl0, bl1);
            }
        }
    }
    {
        int row0 = node0 + warp * 16 + r;
        int row1 = row0 + 8;
        #pragma unroll
        for (int nt = 0; nt < 16; nt++) {
            if (row0 < N_NODES)
                *(float2*)(out + (size_t)row0 * 128 + nt * 8 + 2 * c) =
                    make_float2(d[nt][0], d[nt][1]);
            if (row1 < N_NODES)
                *(float2*)(out + (size_t)row1 * 128 + nt * 8 + 2 * c) =
                    make_float2(d[nt][2], d[nt][3]);
        }
    }
}

// ---------------------------------------------------------------------------
// Echo the passthrough outputs.
// ---------------------------------------------------------------------------
__global__ void tail_copy(float* __restrict__ out,
                          const int*  __restrict__ sn, const int* __restrict__ en,
                          const float* __restrict__ dfs, const float* __restrict__ df)
{
    int i = blockIdx.x * blockDim.x + threadIdx.x;
    float* p = out + OUT_ELEMS;
    if (i < N_EDGES) {
        p[i]               = (float)__ldg(sn + i);
        p[N_EDGES + i]     = (float)__ldg(en + i);
        p[2 * N_EDGES + i] = __ldg(dfs + i);
    }
    if (i < N_NODES)
        p[3 * N_EDGES + i] = __ldg(df + i);
}

extern "C" void kernel_launch(void* const* d_in, const int* in_sizes, int n_in,
                              void* d_out, int out_size)
{
    const float* y   = (const float*)d_in[0];
    const int*   sn  = (const int*)  d_in[1];
    const int*   en  = (const int*)  d_in[2];
    const float* dfs = (const float*)d_in[3];
    const float* df  = (const float*)d_in[4];
    const float* W1  = (const float*)d_in[5];
    const float* b1  = (const float*)d_in[6];
    const float* W2  = (const float*)d_in[7];
    const float* b2  = (const float*)d_in[8];
    float* out = (float*)d_out;

    float *bufA, *bufB;
    cudaGetSymbolAddress((void**)&bufA, g_bufA);
    cudaGetSymbolAddress((void**)&bufB, g_bufB);

    cudaFuncSetAttribute(mlp_kernel, cudaFuncAttributeMaxDynamicSharedMemorySize,
                         MLP_SMEM_WORDS * (int)sizeof(uint32_t));

    const int EB = (N_EDGES + 255) / 256;
    const int GB = (N_NODES * 12 + 255) / 256;

    // ---- CSR build (by destination) ----
    zero_counts<<<(N_NODES + 255) / 256, 256>>>();
    split_weights<<<(128 * 128 + 255) / 256, 256>>>(W1, W2);
    hist_kernel<<<EB, 256>>>(en);
    scanA<<<SCAN_BLOCKS, 256>>>();
    scanB<<<1, 32>>>();
    scanC<<<SCAN_BLOCKS, 256>>>();
    fill_kernel<<<EB, 256>>>(sn, en, dfs);

    // ---- two gather passes (df applied at destination write) ----
    gather_pass<<<GB, 256>>>(y,    bufA, df);
    gather_pass<<<GB, 256>>>(bufA, bufB, df);

    // ---- fused tensor-core MLP ----
    mlp_kernel<<<(N_NODES + MLP_TM - 1) / MLP_TM, MLP_THREADS,
                 MLP_SMEM_WORDS * sizeof(uint32_t)>>>(bufB, b1, b2, out);

    // ---- passthrough echoes ----
    if (out_size >= FULL_OUT) {
        tail_copy<<<EB, 256>>>(out, sn, en, dfs, df);
    }
}

// round 7
// speedup vs baseline: 1.4400x; 1.1122x over previous
#include <cuda_runtime.h>
#include <cstdint>

#define N_NODES 100000
#define N_EDGES 1600000
#define DIN 48
#define DOUT 128
#define OUT_ELEMS (N_NODES * DOUT)                     // 12,800,000
#define FULL_OUT  (OUT_ELEMS + 3 * N_EDGES + N_NODES)  // 17,700,000

#define SCAN_BLOCKS ((N_NODES + 1023) / 1024)          // 98

// Scratch node-feature buffers — written fully by gather, no zeroing.
__device__ float g_bufA[(size_t)N_NODES * DIN];
__device__ float g_bufB[(size_t)N_NODES * DIN];

// CSR-by-destination structures.
__device__ int    g_off[N_NODES + 1];
__device__ int    g_cursor[N_NODES];
__device__ int    g_bsum[SCAN_BLOCKS];
__device__ float2 g_epay[N_EDGES];         // {src_as_float_bits, dfs}

// Pre-split tf32 weights (hi/lo).
__device__ uint32_t g_W1h[48 * 128], g_W1l[48 * 128];
__device__ uint32_t g_W2h[128 * 128], g_W2l[128 * 128];

// ---------------------------------------------------------------------------
// tf32 helpers.
// ---------------------------------------------------------------------------
__device__ __forceinline__ void split_tf32(float x, uint32_t& hi, uint32_t& lo)
{
    float h, l;
    asm("cvt.rna.tf32.f32 %0, %1;" : "=f"(h) : "f"(x));
    float r = x - h;
    asm("cvt.rna.tf32.f32 %0, %1;" : "=f"(l) : "f"(r));
    hi = __float_as_uint(h);
    lo = __float_as_uint(l);
}

__device__ __forceinline__ void mma_tf32(float d[4],
                                         uint32_t a0, uint32_t a1, uint32_t a2, uint32_t a3,
                                         uint32_t b0, uint32_t b1)
{
    asm volatile("mma.sync.aligned.m16n8k8.row.col.f32.tf32.tf32.f32 "
                 "{%0,%1,%2,%3}, {%4,%5,%6,%7}, {%8,%9}, {%0,%1,%2,%3};"
                 : "+f"(d[0]), "+f"(d[1]), "+f"(d[2]), "+f"(d[3])
                 : "r"(a0), "r"(a1), "r"(a2), "r"(a3), "r"(b0), "r"(b1));
}

__global__ void split_weights(const float* __restrict__ W1, const float* __restrict__ W2)
{
    int i = blockIdx.x * blockDim.x + threadIdx.x;
    if (i < 48 * 128)  split_tf32(__ldg(W1 + i), g_W1h[i], g_W1l[i]);
    if (i < 128 * 128) split_tf32(__ldg(W2 + i), g_W2h[i], g_W2l[i]);
}

// ---------------------------------------------------------------------------
// CSR build: memset counts -> histogram -> 3-phase scan -> fill payloads.
// ---------------------------------------------------------------------------
__global__ void hist_kernel(const int* __restrict__ en)
{
    int e = blockIdx.x * blockDim.x + threadIdx.x;
    if (e < N_EDGES) atomicAdd(&g_off[__ldg(en + e)], 1);
}

// Phase A: per-block (1024-item) sums.
__global__ void scanA()
{
    __shared__ int sh[256];
    int tid = threadIdx.x;
    int base = blockIdx.x * 1024 + tid * 4;
    int s = 0;
    #pragma unroll
    for (int j = 0; j < 4; j++)
        s += (base + j < N_NODES) ? g_off[base + j] : 0;
    sh[tid] = s;
    __syncthreads();
    for (int d = 128; d > 0; d >>= 1) {
        if (tid < d) sh[tid] += sh[tid + d];
        __syncthreads();
    }
    if (tid == 0) g_bsum[blockIdx.x] = sh[0];
}

// Phase B: parallel exclusive scan of the 98 block sums (one 128-thread block).
__global__ void scanB()
{
    __shared__ int sh[128];
    int tid = threadIdx.x;
    int v = (tid < SCAN_BLOCKS) ? g_bsum[tid] : 0;
    sh[tid] = v;
    __syncthreads();
    // Hillis-Steele inclusive scan over 128 entries.
    for (int d = 1; d < 128; d <<= 1) {
        int x = (tid >= d) ? sh[tid - d] : 0;
        __syncthreads();
        sh[tid] += x;
        __syncthreads();
    }
    if (tid < SCAN_BLOCKS) g_bsum[tid] = sh[tid] - v;   // exclusive
    if (tid == 127) g_off[N_NODES] = sh[127];           // total == N_EDGES
}

// Phase C: block-local exclusive scan + block prefix; write offsets & cursors.
__global__ void scanC()
{
    __shared__ int sh[256];
    int tid = threadIdx.x;
    int base = blockIdx.x * 1024 + tid * 4;
    int v[4];
    int s = 0;
    #pragma unroll
    for (int j = 0; j < 4; j++) {
        v[j] = (base + j < N_NODES) ? g_off[base + j] : 0;
        s += v[j];
    }
    sh[tid] = s;
    __syncthreads();
    for (int d = 1; d < 256; d <<= 1) {
        int x = (tid >= d) ? sh[tid - d] : 0;
        __syncthreads();
        sh[tid] += x;
        __syncthreads();
    }
    int ex = sh[tid] - s + g_bsum[blockIdx.x];
    #pragma unroll
    for (int j = 0; j < 4; j++) {
        if (base + j < N_NODES) {
            g_off[base + j]    = ex;
            g_cursor[base + j] = ex;
        }
        ex += v[j];
    }
}

__global__ void fill_kernel(const int* __restrict__ sn, const int* __restrict__ en,
                            const float* __restrict__ dfs)
{
    int e = blockIdx.x * blockDim.x + threadIdx.x;
    if (e >= N_EDGES) return;
    int d = __ldg(en + e);
    int pos = atomicAdd(&g_cursor[d], 1);
    g_epay[pos] = make_float2(__int_as_float(__ldg(sn + e)), __ldg(dfs + e));
}

// ---------------------------------------------------------------------------
// Gather pass: dst[n] = df[n] * sum_{e: end=n} src[start_e] * dfs_e
// 12 threads per node, one float4 chunk each. Unrolled x4 for load MLP.
// ---------------------------------------------------------------------------
__global__ void gather_pass(const float* __restrict__ src, float* __restrict__ dst,
                            const float* __restrict__ df)
{
    int t = blockIdx.x * blockDim.x + threadIdx.x;
    if (t >= N_NODES * 12) return;
    int n = t / 12;
    int q = t - n * 12;

    int o0 = __ldg(&g_off[n]);
    int o1 = __ldg(&g_off[n + 1]);

    float4 acc = make_float4(0.f, 0.f, 0.f, 0.f);
    int i = o0;
    for (; i + 4 <= o1; i += 4) {
        float2 p0 = __ldg(&g_epay[i]);
        float2 p1 = __ldg(&g_epay[i + 1]);
        float2 p2 = __ldg(&g_epay[i + 2]);
        float2 p3 = __ldg(&g_epay[i + 3]);
        float4 v0 = __ldg((const float4*)(src + (size_t)__float_as_int(p0.x) * DIN) + q);
        float4 v1 = __ldg((const float4*)(src + (size_t)__float_as_int(p1.x) * DIN) + q);
        float4 v2 = __ldg((const float4*)(src + (size_t)__float_as_int(p2.x) * DIN) + q);
        float4 v3 = __ldg((const float4*)(src + (size_t)__float_as_int(p3.x) * DIN) + q);
        acc.x = fmaf(v0.x, p0.y, acc.x); acc.y = fmaf(v0.y, p0.y, acc.y);
        acc.z = fmaf(v0.z, p0.y, acc.z); acc.w = fmaf(v0.w, p0.y, acc.w);
        acc.x = fmaf(v1.x, p1.y, acc.x); acc.y = fmaf(v1.y, p1.y, acc.y);
        acc.z = fmaf(v1.z, p1.y, acc.z); acc.w = fmaf(v1.w, p1.y, acc.w);
        acc.x = fmaf(v2.x, p2.y, acc.x); acc.y = fmaf(v2.y, p2.y, acc.y);
        acc.z = fmaf(v2.z, p2.y, acc.z); acc.w = fmaf(v2.w, p2.y, acc.w);
        acc.x = fmaf(v3.x, p3.y, acc.x); acc.y = fmaf(v3.y, p3.y, acc.y);
        acc.z = fmaf(v3.z, p3.y, acc.z); acc.w = fmaf(v3.w, p3.y, acc.w);
    }
    for (; i < o1; i++) {
        float2 p = __ldg(&g_epay[i]);
        float4 v = __ldg((const float4*)(src + (size_t)__float_as_int(p.x) * DIN) + q);
        acc.x = fmaf(v.x, p.y, acc.x); acc.y = fmaf(v.y, p.y, acc.y);
        acc.z = fmaf(v.z, p.y, acc.z); acc.w = fmaf(v.w, p.y, acc.w);
    }

    float f = __ldg(df + n);
    acc.x *= f; acc.y *= f; acc.z *= f; acc.w *= f;
    ((float4*)(dst + (size_t)n * DIN))[q] = acc;
}

// ---------------------------------------------------------------------------
// Persistent fused MLP on tensor cores (tf32 mma.sync, 3xTF32 compensation):
//   out = relu(x @ W1 + b1) @ W2 + b2
// 148 CTAs; weights staged into smem ONCE per CTA, then loop over node tiles.
// ---------------------------------------------------------------------------
#define MLP_TM 128
#define MLP_THREADS 256
#define MLP_GRID 148
#define N_TILES ((N_NODES + MLP_TM - 1) / MLP_TM)      // 782
#define W_STRIDE 136
#define YT_STRIDE 52
#define MLP_SMEM_WORDS (48*W_STRIDE*2 + 128*W_STRIDE*2 + 256 + MLP_TM*YT_STRIDE)

__global__ void __launch_bounds__(MLP_THREADS, 1)
mlp_kernel(const float* __restrict__ x,
           const float* __restrict__ b1, const float* __restrict__ b2,
           float* __restrict__ out)
{
    extern __shared__ uint32_t smu[];
    uint32_t* W1hs = smu;                         // [48][136]
    uint32_t* W1ls = W1hs + 48 * W_STRIDE;
    uint32_t* W2hs = W1ls + 48 * W_STRIDE;        // [128][136]
    uint32_t* W2ls = W2hs + 128 * W_STRIDE;
    float*    b1s  = (float*)(W2ls + 128 * W_STRIDE);
    float*    b2s  = b1s + 128;
    float*    yt   = b2s + 128;                   // [128][52]

    int tid = threadIdx.x;

    // Stage weights/biases once per CTA.
    for (int i = tid; i < 48 * 128; i += MLP_THREADS) {
        int k = i >> 7, n = i & 127;
        W1hs[k * W_STRIDE + n] = g_W1h[i];
        W1ls[k * W_STRIDE + n] = g_W1l[i];
    }
    for (int i = tid; i < 128 * 128; i += MLP_THREADS) {
        int k = i >> 7, n = i & 127;
        W2hs[k * W_STRIDE + n] = g_W2h[i];
        W2ls[k * W_STRIDE + n] = g_W2l[i];
    }
    if (tid < 128) { b1s[tid] = __ldg(b1 + tid); b2s[tid] = __ldg(b2 + tid); }

    int warp = tid >> 5;
    int lane = tid & 31;
    int r = lane >> 2;
    int c = lane & 3;
    int srcA = (lane & ~3) | (c >> 1);
    int srcB = srcA + 2;
    bool odd = (c & 1);

    for (int tile = blockIdx.x; tile < N_TILES; tile += MLP_GRID) {
        int node0 = tile * MLP_TM;

        __syncthreads();   // previous iteration's yt reads done
        for (int i = tid; i < MLP_TM * 48; i += MLP_THREADS) {
            int rr = i / 48;
            int n = node0 + rr;
            yt[rr * YT_STRIDE + (i - rr * 48)] =
                (n < N_NODES) ? __ldg(x + (size_t)n * 48 + (i - rr * 48)) : 0.f;
        }
        __syncthreads();

        float d[16][4];
        float h[16][4];

        // ---- stage 1: H = relu(Y @ W1 + b1), K = 48 ----
        #pragma unroll
        for (int nt = 0; nt < 16; nt++) {
            d[nt][0] = b1s[nt * 8 + 2 * c];
            d[nt][1] = b1s[nt * 8 + 2 * c + 1];
            d[nt][2] = d[nt][0];
            d[nt][3] = d[nt][1];
        }
        {
            const float* yb = yt + warp * 16 * YT_STRIDE;
            #pragma unroll
            for (int ks = 0; ks < 6; ks++) {
                int k0 = ks * 8;
                uint32_t ah[4], al[4];
                split_tf32(yb[r * YT_STRIDE + k0 + c],           ah[0], al[0]);
                split_tf32(yb[(r + 8) * YT_STRIDE + k0 + c],     ah[1], al[1]);
                split_tf32(yb[r * YT_STRIDE + k0 + c + 4],       ah[2], al[2]);
                split_tf32(yb[(r + 8) * YT_STRIDE + k0 + c + 4], ah[3], al[3]);
                #pragma unroll
                for (int nt = 0; nt < 16; nt++) {
                    uint32_t bh0 = W1hs[(k0 + c) * W_STRIDE + nt * 8 + r];
                    uint32_t bh1 = W1hs[(k0 + c + 4) * W_STRIDE + nt * 8 + r];
                    uint32_t bl0 = W1ls[(k0 + c) * W_STRIDE + nt * 8 + r];
                    uint32_t bl1 = W1ls[(k0 + c + 4) * W_STRIDE + nt * 8 + r];
                    mma_tf32(d[nt], ah[0], ah[1], ah[2], ah[3], bh0, bh1);
                    mma_tf32(d[nt], al[0], al[1], al[2], al[3], bh0, bh1);
                    mma_tf32(d[nt], ah[0], ah[1], ah[2], ah[3], bl0, bl1);
                }
            }
        }
        #pragma unroll
        for (int nt = 0; nt < 16; nt++) {
            h[nt][0] = fmaxf(d[nt][0], 0.f);
            h[nt][1] = fmaxf(d[nt][1], 0.f);
            h[nt][2] = fmaxf(d[nt][2], 0.f);
            h[nt][3] = fmaxf(d[nt][3], 0.f);
        }

        // ---- stage 2: OUT = H @ W2 + b2, K = 128 ----
        #pragma unroll
        for (int nt = 0; nt < 16; nt++) {
            d[nt][0] = b2s[nt * 8 + 2 * c];
            d[nt][1] = b2s[nt * 8 + 2 * c + 1];
            d[nt][2] = d[nt][0];
            d[nt][3] = d[nt][1];
        }
        #pragma unroll
        for (int ks = 0; ks < 16; ks++) {
            int k0 = ks * 8;
            float w0 = __shfl_sync(0xFFFFFFFFu, h[ks][0], srcA);
            float w1 = __shfl_sync(0xFFFFFFFFu, h[ks][1], srcA);
            float w2 = __shfl_sync(0xFFFFFFFFu, h[ks][2], srcA);
            float w3 = __shfl_sync(0xFFFFFFFFu, h[ks][3], srcA);
            float x0 = __shfl_sync(0xFFFFFFFFu, h[ks][0], srcB);
            float x1 = __shfl_sync(0xFFFFFFFFu, h[ks][1], srcB);
            float x2 = __shfl_sync(0xFFFFFFFFu, h[ks][2], srcB);
            float x3 = __shfl_sync(0xFFFFFFFFu, h[ks][3], srcB);
            uint32_t ah[4], al[4];
            split_tf32(odd ? w1 : w0, ah[0], al[0]);
            split_tf32(odd ? w3 : w2, ah[1], al[1]);
            split_tf32(odd ? x1 : x0, ah[2], al[2]);
            split_tf32(odd ? x3 : x2, ah[3], al[3]);
            #pragma unroll
            for (int nt = 0; nt < 16; nt++) {
                uint32_t bh0 = W2hs[(k0 + c) * W_STRIDE + nt * 8 + r];
                uint32_t bh1 = W2hs[(k0 + c + 4) * W_STRIDE + nt * 8 + r];
                uint32_t bl0 = W2ls[(k0 + c) * W_STRIDE + nt * 8 + r];
                uint32_t bl1 = W2ls[(k0 + c + 4) * W_STRIDE + nt * 8 + r];
                mma_tf32(d[nt], ah[0], ah[1], ah[2], ah[3], bh0, bh1);
                mma_tf32(d[nt], al[0], al[1], al[2], al[3], bh0, bh1);
                mma_tf32(d[nt], ah[0], ah[1], ah[2], ah[3], bl0, bl1);
            }
        }
        {
            int row0 = node0 + warp * 16 + r;
            int row1 = row0 + 8;
            #pragma unroll
            for (int nt = 0; nt < 16; nt++) {
                if (row0 < N_NODES)
                    *(float2*)(out + (size_t)row0 * 128 + nt * 8 + 2 * c) =
                        make_float2(d[nt][0], d[nt][1]);
                if (row1 < N_NODES)
                    *(float2*)(out + (size_t)row1 * 128 + nt * 8 + 2 * c) =
                        make_float2(d[nt][2], d[nt][3]);
            }
        }
    }
}

// ---------------------------------------------------------------------------
// Echo the passthrough outputs.
// ---------------------------------------------------------------------------
__global__ void tail_copy(float* __restrict__ out,
                          const int*  __restrict__ sn, const int* __restrict__ en,
                          const float* __restrict__ dfs, const float* __restrict__ df)
{
    int i = blockIdx.x * blockDim.x + threadIdx.x;
    float* p = out + OUT_ELEMS;
    if (i < N_EDGES) {
        p[i]               = (float)__ldg(sn + i);
        p[N_EDGES + i]     = (float)__ldg(en + i);
        p[2 * N_EDGES + i] = __ldg(dfs + i);
    }
    if (i < N_NODES)
        p[3 * N_EDGES + i] = __ldg(df + i);
}

extern "C" void kernel_launch(void* const* d_in, const int* in_sizes, int n_in,
                              void* d_out, int out_size)
{
    const float* y   = (const float*)d_in[0];
    const int*   sn  = (const int*)  d_in[1];
    const int*   en  = (const int*)  d_in[2];
    const float* dfs = (const float*)d_in[3];
    const float* df  = (const float*)d_in[4];
    const float* W1  = (const float*)d_in[5];
    const float* b1  = (const float*)d_in[6];
    const float* W2  = (const float*)d_in[7];
    const float* b2  = (const float*)d_in[8];
    float* out = (float*)d_out;

    float *bufA, *bufB;
    cudaGetSymbolAddress((void**)&bufA, g_bufA);
    cudaGetSymbolAddress((void**)&bufB, g_bufB);
    int* offp;
    cudaGetSymbolAddress((void**)&offp, g_off);

    cudaFuncSetAttribute(mlp_kernel, cudaFuncAttributeMaxDynamicSharedMemorySize,
                         MLP_SMEM_WORDS * (int)sizeof(uint32_t));

    const int EB = (N_EDGES + 255) / 256;
    const int GB = (N_NODES * 12 + 255) / 256;

    // ---- CSR build (by destination) ----
    cudaMemsetAsync(offp, 0, N_NODES * sizeof(int));
    split_weights<<<(128 * 128 + 255) / 256, 256>>>(W1, W2);
    hist_kernel<<<EB, 256>>>(en);
    scanA<<<SCAN_BLOCKS, 256>>>();
    scanB<<<1, 128>>>();
    scanC<<<SCAN_BLOCKS, 256>>>();
    fill_kernel<<<EB, 256>>>(sn, en, dfs);

    // ---- two gather passes (df applied at destination write) ----
    gather_pass<<<GB, 256>>>(y,    bufA, df);
    gather_pass<<<GB, 256>>>(bufA, bufB, df);

    // ---- persistent fused tensor-core MLP ----
    mlp_kernel<<<MLP_GRID, MLP_THREADS,
                 MLP_SMEM_WORDS * sizeof(uint32_t)>>>(bufB, b1, b2, out);

    // ---- passthrough echoes ----
    if (out_size >= FULL_OUT) {
        tail_copy<<<EB, 256>>>(out, sn, en, dfs, df);
    }
}

// round 8
// speedup vs baseline: 1.4590x; 1.0132x over previous
#include <cuda_runtime.h>
#include <cstdint>

#define N_NODES 100000
#define N_EDGES 1600000
#define DIN 48
#define DOUT 128
#define OUT_ELEMS (N_NODES * DOUT)                     // 12,800,000
#define FULL_OUT  (OUT_ELEMS + 3 * N_EDGES + N_NODES)  // 17,700,000

#define SCAN_BLOCKS ((N_NODES + 1023) / 1024)          // 98

// Scratch node-feature buffers — written fully by gather, no zeroing.
__device__ float g_bufA[(size_t)N_NODES * DIN];
__device__ float g_bufB[(size_t)N_NODES * DIN];

// CSR-by-destination structures.
__device__ int    g_off[N_NODES + 1];
__device__ int    g_cursor[N_NODES];
__device__ int    g_bsum[SCAN_BLOCKS];
__device__ int    g_scan_ctr;              // zero-init; reset by last block
__device__ float2 g_epay[N_EDGES];         // {src_as_float_bits, dfs}

// Pre-split tf32 weights (hi/lo).
__device__ uint32_t g_W1h[48 * 128], g_W1l[48 * 128];
__device__ uint32_t g_W2h[128 * 128], g_W2l[128 * 128];

// ---------------------------------------------------------------------------
// tf32 helpers.
// ---------------------------------------------------------------------------
__device__ __forceinline__ void split_tf32(float x, uint32_t& hi, uint32_t& lo)
{
    float h, l;
    asm("cvt.rna.tf32.f32 %0, %1;" : "=f"(h) : "f"(x));
    float r = x - h;
    asm("cvt.rna.tf32.f32 %0, %1;" : "=f"(l) : "f"(r));
    hi = __float_as_uint(h);
    lo = __float_as_uint(l);
}

__device__ __forceinline__ void mma_tf32(float d[4],
                                         uint32_t a0, uint32_t a1, uint32_t a2, uint32_t a3,
                                         uint32_t b0, uint32_t b1)
{
    asm volatile("mma.sync.aligned.m16n8k8.row.col.f32.tf32.tf32.f32 "
                 "{%0,%1,%2,%3}, {%4,%5,%6,%7}, {%8,%9}, {%0,%1,%2,%3};"
                 : "+f"(d[0]), "+f"(d[1]), "+f"(d[2]), "+f"(d[3])
                 : "r"(a0), "r"(a1), "r"(a2), "r"(a3), "r"(b0), "r"(b1));
}

// ---------------------------------------------------------------------------
// hist + split_weights fused (independent work in extra blocks).
// Blocks [0, EB): histogram of end-node degrees.
// Blocks [EB, EB+64): one-time tf32 weight split.
// ---------------------------------------------------------------------------
#define EB ((N_EDGES + 255) / 256)         // 6250
#define WB 64                               // 16384 / 256

__global__ void hist_and_split(const int* __restrict__ en,
                               const float* __restrict__ W1, const float* __restrict__ W2)
{
    if (blockIdx.x < EB) {
        int e = blockIdx.x * blockDim.x + threadIdx.x;
        if (e < N_EDGES) atomicAdd(&g_off[__ldg(en + e)], 1);
    } else {
        int i = (blockIdx.x - EB) * blockDim.x + threadIdx.x;
        if (i < 48 * 128)  split_tf32(__ldg(W1 + i), g_W1h[i], g_W1l[i]);
        if (i < 128 * 128) split_tf32(__ldg(W2 + i), g_W2h[i], g_W2l[i]);
    }
}

// ---------------------------------------------------------------------------
// scanA+scanB fused: per-block sums, then the LAST block to finish scans the
// 98 block sums (threadfence + counter handoff, L1-bypass reads).
// ---------------------------------------------------------------------------
__global__ void scanAB()
{
    __shared__ int sh[256];
    __shared__ bool is_last;
    int tid = threadIdx.x;
    int base = blockIdx.x * 1024 + tid * 4;
    int s = 0;
    #pragma unroll
    for (int j = 0; j < 4; j++)
        s += (base + j < N_NODES) ? g_off[base + j] : 0;
    sh[tid] = s;
    __syncthreads();
    for (int d = 128; d > 0; d >>= 1) {
        if (tid < d) sh[tid] += sh[tid + d];
        __syncthreads();
    }
    if (tid == 0) {
        g_bsum[blockIdx.x] = sh[0];
        __threadfence();
        int c = atomicAdd(&g_scan_ctr, 1);
        is_last = (c == gridDim.x - 1);
    }
    __syncthreads();
    if (!is_last) return;

    // Exclusive scan of block sums (values beyond SCAN_BLOCKS are 0).
    int v = (tid < SCAN_BLOCKS) ? __ldcg(&g_bsum[tid]) : 0;
    __syncthreads();
    sh[tid] = v;
    __syncthreads();
    for (int d = 1; d < 256; d <<= 1) {
        int x = (tid >= d) ? sh[tid - d] : 0;
        __syncthreads();
        sh[tid] += x;
        __syncthreads();
    }
    if (tid < SCAN_BLOCKS) g_bsum[tid] = sh[tid] - v;
    if (tid == 0) { g_off[N_NODES] = sh[255]; g_scan_ctr = 0; }  // reset for replay
}

// Phase C: block-local exclusive scan + block prefix; write offsets & cursors.
__global__ void scanC()
{
    __shared__ int sh[256];
    int tid = threadIdx.x;
    int base = blockIdx.x * 1024 + tid * 4;
    int v[4];
    int s = 0;
    #pragma unroll
    for (int j = 0; j < 4; j++) {
        v[j] = (base + j < N_NODES) ? g_off[base + j] : 0;
        s += v[j];
    }
    sh[tid] = s;
    __syncthreads();
    for (int d = 1; d < 256; d <<= 1) {
        int x = (tid >= d) ? sh[tid - d] : 0;
        __syncthreads();
        sh[tid] += x;
        __syncthreads();
    }
    int ex = sh[tid] - s + g_bsum[blockIdx.x];
    #pragma unroll
    for (int j = 0; j < 4; j++) {
        if (base + j < N_NODES) {
            g_off[base + j]    = ex;
            g_cursor[base + j] = ex;
        }
        ex += v[j];
    }
}

__global__ void fill_kernel(const int* __restrict__ sn, const int* __restrict__ en,
                            const float* __restrict__ dfs)
{
    int e = blockIdx.x * blockDim.x + threadIdx.x;
    if (e >= N_EDGES) return;
    int d = __ldg(en + e);
    int pos = atomicAdd(&g_cursor[d], 1);
    g_epay[pos] = make_float2(__int_as_float(__ldg(sn + e)), __ldg(dfs + e));
}

// ---------------------------------------------------------------------------
// Gather pass: dst[n] = df[n] * sum_{e: end=n} src[start_e] * dfs_e
// 12 threads per node, one float4 chunk each, unrolled x4.
// TAIL variant: blocks >= GB instead run the passthrough echo (overlaps the
// DRAM-writing tail with the L2-bound gather).
// ---------------------------------------------------------------------------
#define GB ((N_NODES * 12 + 255) / 256)     // 4688

template <bool TAIL>
__global__ void gather_pass(const float* __restrict__ src, float* __restrict__ dst,
                            const float* __restrict__ df,
                            const int*  __restrict__ sn, const int* __restrict__ en,
                            const float* __restrict__ dfs, float* __restrict__ out)
{
    if (TAIL && blockIdx.x >= GB) {
        int i = (blockIdx.x - GB) * blockDim.x + threadIdx.x;
        float* p = out + OUT_ELEMS;
        if (i < N_EDGES) {
            p[i]               = (float)__ldg(sn + i);
            p[N_EDGES + i]     = (float)__ldg(en + i);
            p[2 * N_EDGES + i] = __ldg(dfs + i);
        }
        if (i < N_NODES)
            p[3 * N_EDGES + i] = __ldg(df + i);
        return;
    }

    int t = blockIdx.x * blockDim.x + threadIdx.x;
    if (t >= N_NODES * 12) return;
    int n = t / 12;
    int q = t - n * 12;

    int o0 = __ldg(&g_off[n]);
    int o1 = __ldg(&g_off[n + 1]);

    float4 acc = make_float4(0.f, 0.f, 0.f, 0.f);
    int i = o0;
    for (; i + 4 <= o1; i += 4) {
        float2 p0 = __ldg(&g_epay[i]);
        float2 p1 = __ldg(&g_epay[i + 1]);
        float2 p2 = __ldg(&g_epay[i + 2]);
        float2 p3 = __ldg(&g_epay[i + 3]);
        float4 v0 = __ldg((const float4*)(src + (size_t)__float_as_int(p0.x) * DIN) + q);
        float4 v1 = __ldg((const float4*)(src + (size_t)__float_as_int(p1.x) * DIN) + q);
        float4 v2 = __ldg((const float4*)(src + (size_t)__float_as_int(p2.x) * DIN) + q);
        float4 v3 = __ldg((const float4*)(src + (size_t)__float_as_int(p3.x) * DIN) + q);
        acc.x = fmaf(v0.x, p0.y, acc.x); acc.y = fmaf(v0.y, p0.y, acc.y);
        acc.z = fmaf(v0.z, p0.y, acc.z); acc.w = fmaf(v0.w, p0.y, acc.w);
        acc.x = fmaf(v1.x, p1.y, acc.x); acc.y = fmaf(v1.y, p1.y, acc.y);
        acc.z = fmaf(v1.z, p1.y, acc.z); acc.w = fmaf(v1.w, p1.y, acc.w);
        acc.x = fmaf(v2.x, p2.y, acc.x); acc.y = fmaf(v2.y, p2.y, acc.y);
        acc.z = fmaf(v2.z, p2.y, acc.z); acc.w = fmaf(v2.w, p2.y, acc.w);
        acc.x = fmaf(v3.x, p3.y, acc.x); acc.y = fmaf(v3.y, p3.y, acc.y);
        acc.z = fmaf(v3.z, p3.y, acc.z); acc.w = fmaf(v3.w, p3.y, acc.w);
    }
    for (; i < o1; i++) {
        float2 p = __ldg(&g_epay[i]);
        float4 v = __ldg((const float4*)(src + (size_t)__float_as_int(p.x) * DIN) + q);
        acc.x = fmaf(v.x, p.y, acc.x); acc.y = fmaf(v.y, p.y, acc.y);
        acc.z = fmaf(v.z, p.y, acc.z); acc.w = fmaf(v.w, p.y, acc.w);
    }

    float f = __ldg(df + n);
    acc.x *= f; acc.y *= f; acc.z *= f; acc.w *= f;
    ((float4*)(dst + (size_t)n * DIN))[q] = acc;
}

// ---------------------------------------------------------------------------
// Persistent fused MLP on tensor cores (tf32 mma.sync, 3xTF32 compensation):
//   out = relu(x @ W1 + b1) @ W2 + b2
// 148 CTAs; weights staged into smem ONCE per CTA, then loop over node tiles.
// ---------------------------------------------------------------------------
#define MLP_TM 128
#define MLP_THREADS 256
#define MLP_GRID 148
#define N_TILES ((N_NODES + MLP_TM - 1) / MLP_TM)      // 782
#define W_STRIDE 136
#define YT_STRIDE 52
#define MLP_SMEM_WORDS (48*W_STRIDE*2 + 128*W_STRIDE*2 + 256 + MLP_TM*YT_STRIDE)

__global__ void __launch_bounds__(MLP_THREADS, 1)
mlp_kernel(const float* __restrict__ x,
           const float* __restrict__ b1, const float* __restrict__ b2,
           float* __restrict__ out)
{
    extern __shared__ uint32_t smu[];
    uint32_t* W1hs = smu;                         // [48][136]
    uint32_t* W1ls = W1hs + 48 * W_STRIDE;
    uint32_t* W2hs = W1ls + 48 * W_STRIDE;        // [128][136]
    uint32_t* W2ls = W2hs + 128 * W_STRIDE;
    float*    b1s  = (float*)(W2ls + 128 * W_STRIDE);
    float*    b2s  = b1s + 128;
    float*    yt   = b2s + 128;                   // [128][52]

    int tid = threadIdx.x;

    for (int i = tid; i < 48 * 128; i += MLP_THREADS) {
        int k = i >> 7, n = i & 127;
        W1hs[k * W_STRIDE + n] = g_W1h[i];
        W1ls[k * W_STRIDE + n] = g_W1l[i];
    }
    for (int i = tid; i < 128 * 128; i += MLP_THREADS) {
        int k = i >> 7, n = i & 127;
        W2hs[k * W_STRIDE + n] = g_W2h[i];
        W2ls[k * W_STRIDE + n] = g_W2l[i];
    }
    if (tid < 128) { b1s[tid] = __ldg(b1 + tid); b2s[tid] = __ldg(b2 + tid); }

    int warp = tid >> 5;
    int lane = tid & 31;
    int r = lane >> 2;
    int c = lane & 3;
    int srcA = (lane & ~3) | (c >> 1);
    int srcB = srcA + 2;
    bool odd = (c & 1);

    for (int tile = blockIdx.x; tile < N_TILES; tile += MLP_GRID) {
        int node0 = tile * MLP_TM;

        __syncthreads();
        for (int i = tid; i < MLP_TM * 48; i += MLP_THREADS) {
            int rr = i / 48;
            int n = node0 + rr;
            yt[rr * YT_STRIDE + (i - rr * 48)] =
                (n < N_NODES) ? __ldg(x + (size_t)n * 48 + (i - rr * 48)) : 0.f;
        }
        __syncthreads();

        float d[16][4];
        float h[16][4];

        // ---- stage 1: H = relu(Y @ W1 + b1), K = 48 ----
        #pragma unroll
        for (int nt = 0; nt < 16; nt++) {
            d[nt][0] = b1s[nt * 8 + 2 * c];
            d[nt][1] = b1s[nt * 8 + 2 * c + 1];
            d[nt][2] = d[nt][0];
            d[nt][3] = d[nt][1];
        }
        {
            const float* yb = yt + warp * 16 * YT_STRIDE;
            #pragma unroll
            for (int ks = 0; ks < 6; ks++) {
                int k0 = ks * 8;
                uint32_t ah[4], al[4];
                split_tf32(yb[r * YT_STRIDE + k0 + c],           ah[0], al[0]);
                split_tf32(yb[(r + 8) * YT_STRIDE + k0 + c],     ah[1], al[1]);
                split_tf32(yb[r * YT_STRIDE + k0 + c + 4],       ah[2], al[2]);
                split_tf32(yb[(r + 8) * YT_STRIDE + k0 + c + 4], ah[3], al[3]);
                #pragma unroll
                for (int nt = 0; nt < 16; nt++) {
                    uint32_t bh0 = W1hs[(k0 + c) * W_STRIDE + nt * 8 + r];
                    uint32_t bh1 = W1hs[(k0 + c + 4) * W_STRIDE + nt * 8 + r];
                    uint32_t bl0 = W1ls[(k0 + c) * W_STRIDE + nt * 8 + r];
                    uint32_t bl1 = W1ls[(k0 + c + 4) * W_STRIDE + nt * 8 + r];
                    mma_tf32(d[nt], ah[0], ah[1], ah[2], ah[3], bh0, bh1);
                    mma_tf32(d[nt], al[0], al[1], al[2], al[3], bh0, bh1);
                    mma_tf32(d[nt], ah[0], ah[1], ah[2], ah[3], bl0, bl1);
                }
            }
        }
        #pragma unroll
        for (int nt = 0; nt < 16; nt++) {
            h[nt][0] = fmaxf(d[nt][0], 0.f);
            h[nt][1] = fmaxf(d[nt][1], 0.f);
            h[nt][2] = fmaxf(d[nt][2], 0.f);
            h[nt][3] = fmaxf(d[nt][3], 0.f);
        }

        // ---- stage 2: OUT = H @ W2 + b2, K = 128 ----
        #pragma unroll
        for (int nt = 0; nt < 16; nt++) {
            d[nt][0] = b2s[nt * 8 + 2 * c];
            d[nt][1] = b2s[nt * 8 + 2 * c + 1];
            d[nt][2] = d[nt][0];
            d[nt][3] = d[nt][1];
        }
        #pragma unroll
        for (int ks = 0; ks < 16; ks++) {
            int k0 = ks * 8;
            float w0 = __shfl_sync(0xFFFFFFFFu, h[ks][0], srcA);
            float w1 = __shfl_sync(0xFFFFFFFFu, h[ks][1], srcA);
            float w2 = __shfl_sync(0xFFFFFFFFu, h[ks][2], srcA);
            float w3 = __shfl_sync(0xFFFFFFFFu, h[ks][3], srcA);
            float x0 = __shfl_sync(0xFFFFFFFFu, h[ks][0], srcB);
            float x1 = __shfl_sync(0xFFFFFFFFu, h[ks][1], srcB);
            float x2 = __shfl_sync(0xFFFFFFFFu, h[ks][2], srcB);
            float x3 = __shfl_sync(0xFFFFFFFFu, h[ks][3], srcB);
            uint32_t ah[4], al[4];
            split_tf32(odd ? w1 : w0, ah[0], al[0]);
            split_tf32(odd ? w3 : w2, ah[1], al[1]);
            split_tf32(odd ? x1 : x0, ah[2], al[2]);
            split_tf32(odd ? x3 : x2, ah[3], al[3]);
            #pragma unroll
            for (int nt = 0; nt < 16; nt++) {
                uint32_t bh0 = W2hs[(k0 + c) * W_STRIDE + nt * 8 + r];
                uint32_t bh1 = W2hs[(k0 + c + 4) * W_STRIDE + nt * 8 + r];
                uint32_t bl0 = W2ls[(k0 + c) * W_STRIDE + nt * 8 + r];
                uint32_t bl1 = W2ls[(k0 + c + 4) * W_STRIDE + nt * 8 + r];
                mma_tf32(d[nt], ah[0], ah[1], ah[2], ah[3], bh0, bh1);
                mma_tf32(d[nt], al[0], al[1], al[2], al[3], bh0, bh1);
                mma_tf32(d[nt], ah[0], ah[1], ah[2], ah[3], bl0, bl1);
            }
        }
        {
            int row0 = node0 + warp * 16 + r;
            int row1 = row0 + 8;
            #pragma unroll
            for (int nt = 0; nt < 16; nt++) {
                if (row0 < N_NODES)
                    *(float2*)(out + (size_t)row0 * 128 + nt * 8 + 2 * c) =
                        make_float2(d[nt][0], d[nt][1]);
                if (row1 < N_NODES)
                    *(float2*)(out + (size_t)row1 * 128 + nt * 8 + 2 * c) =
                        make_float2(d[nt][2], d[nt][3]);
            }
        }
    }
}

extern "C" void kernel_launch(void* const* d_in, const int* in_sizes, int n_in,
                              void* d_out, int out_size)
{
    const float* y   = (const float*)d_in[0];
    const int*   sn  = (const int*)  d_in[1];
    const int*   en  = (const int*)  d_in[2];
    const float* dfs = (const float*)d_in[3];
    const float* df  = (const float*)d_in[4];
    const float* W1  = (const float*)d_in[5];
    const float* b1  = (const float*)d_in[6];
    const float* W2  = (const float*)d_in[7];
    const float* b2  = (const float*)d_in[8];
    float* out = (float*)d_out;

    float *bufA, *bufB;
    cudaGetSymbolAddress((void**)&bufA, g_bufA);
    cudaGetSymbolAddress((void**)&bufB, g_bufB);
    int* offp;
    cudaGetSymbolAddress((void**)&offp, g_off);

    cudaFuncSetAttribute(mlp_kernel, cudaFuncAttributeMaxDynamicSharedMemorySize,
                         MLP_SMEM_WORDS * (int)sizeof(uint32_t));

    // ---- CSR build (by destination), weight split overlapped ----
    cudaMemsetAsync(offp, 0, N_NODES * sizeof(int));
    hist_and_split<<<EB + WB, 256>>>(en, W1, W2);
    scanAB<<<SCAN_BLOCKS, 256>>>();
    scanC<<<SCAN_BLOCKS, 256>>>();
    fill_kernel<<<EB, 256>>>(sn, en, dfs);

    // ---- gather pass 1 with overlapped passthrough echo ----
    if (out_size >= FULL_OUT) {
        gather_pass<true><<<GB + EB, 256>>>(y, bufA, df, sn, en, dfs, out);
    } else {
        gather_pass<false><<<GB, 256>>>(y, bufA, df, sn, en, dfs, out);
    }

    // ---- gather pass 2 ----
    gather_pass<false><<<GB, 256>>>(bufA, bufB, df, sn, en, dfs, out);

    // ---- persistent fused tensor-core MLP ----
    mlp_kernel<<<MLP_GRID, MLP_THREADS,
                 MLP_SMEM_WORDS * sizeof(uint32_t)>>>(bufB, b1, b2, out);
}

// round 9
// speedup vs baseline: 1.4779x; 1.0129x over previous
#include <cuda_runtime.h>
#include <cstdint>

#define N_NODES 100000
#define N_EDGES 1600000
#define DIN 48
#define DOUT 128
#define OUT_ELEMS (N_NODES * DOUT)                     // 12,800,000
#define FULL_OUT  (OUT_ELEMS + 3 * N_EDGES + N_NODES)  // 17,700,000

#define SCAN_BLOCKS ((N_NODES + 1023) / 1024)          // 98

// Scratch node-feature buffers — written fully by gather, no zeroing.
__device__ float g_bufA[(size_t)N_NODES * DIN];
__device__ float g_bufB[(size_t)N_NODES * DIN];

// CSR-by-destination structures.
__device__ int    g_off[N_NODES + 1];
__device__ int    g_cursor[N_NODES];
__device__ int    g_bsum[SCAN_BLOCKS];
__device__ int    g_scan_ctr;              // zero-init; reset by last block
__device__ float2 g_epay[N_EDGES];         // {src_as_float_bits, dfs}

// Pre-split tf32 weights (hi/lo).
__device__ uint32_t g_W1h[48 * 128], g_W1l[48 * 128];
__device__ uint32_t g_W2h[128 * 128], g_W2l[128 * 128];

// ---------------------------------------------------------------------------
// tf32 helpers.
// ---------------------------------------------------------------------------
__device__ __forceinline__ void split_tf32(float x, uint32_t& hi, uint32_t& lo)
{
    float h, l;
    asm("cvt.rna.tf32.f32 %0, %1;" : "=f"(h) : "f"(x));
    float r = x - h;
    asm("cvt.rna.tf32.f32 %0, %1;" : "=f"(l) : "f"(r));
    hi = __float_as_uint(h);
    lo = __float_as_uint(l);
}

__device__ __forceinline__ void mma_tf32(float d[4],
                                         uint32_t a0, uint32_t a1, uint32_t a2, uint32_t a3,
                                         uint32_t b0, uint32_t b1)
{
    asm volatile("mma.sync.aligned.m16n8k8.row.col.f32.tf32.tf32.f32 "
                 "{%0,%1,%2,%3}, {%4,%5,%6,%7}, {%8,%9}, {%0,%1,%2,%3};"
                 : "+f"(d[0]), "+f"(d[1]), "+f"(d[2]), "+f"(d[3])
                 : "r"(a0), "r"(a1), "r"(a2), "r"(a3), "r"(b0), "r"(b1));
}

// ---------------------------------------------------------------------------
// hist (x4 edges/thread, return-less atomics -> REDG) + weight split fused.
// ---------------------------------------------------------------------------
#define EB4 (N_EDGES / 4 / 256)             // 1562.5 -> 1563
#define HB  ((N_EDGES / 4 + 255) / 256)     // 1563
#define WB  64                              // 16384 / 256

__global__ void hist_and_split(const int* __restrict__ en,
                               const float* __restrict__ W1, const float* __restrict__ W2)
{
    if (blockIdx.x < HB) {
        int e0 = (blockIdx.x * blockDim.x + threadIdx.x) * 4;
        if (e0 + 4 <= N_EDGES) {
            int4 d4 = *(const int4*)(en + e0);
            atomicAdd(&g_off[d4.x], 1);
            atomicAdd(&g_off[d4.y], 1);
            atomicAdd(&g_off[d4.z], 1);
            atomicAdd(&g_off[d4.w], 1);
        } else {
            for (int e = e0; e < N_EDGES; e++)
                atomicAdd(&g_off[__ldg(en + e)], 1);
        }
    } else {
        int i = (blockIdx.x - HB) * blockDim.x + threadIdx.x;
        if (i < 48 * 128)  split_tf32(__ldg(W1 + i), g_W1h[i], g_W1l[i]);
        if (i < 128 * 128) split_tf32(__ldg(W2 + i), g_W2h[i], g_W2l[i]);
    }
}

// ---------------------------------------------------------------------------
// scanA+scanB fused (last-block-arrival pattern).
// ---------------------------------------------------------------------------
__global__ void scanAB()
{
    __shared__ int sh[256];
    __shared__ bool is_last;
    int tid = threadIdx.x;
    int base = blockIdx.x * 1024 + tid * 4;
    int s = 0;
    #pragma unroll
    for (int j = 0; j < 4; j++)
        s += (base + j < N_NODES) ? g_off[base + j] : 0;
    sh[tid] = s;
    __syncthreads();
    for (int d = 128; d > 0; d >>= 1) {
        if (tid < d) sh[tid] += sh[tid + d];
        __syncthreads();
    }
    if (tid == 0) {
        g_bsum[blockIdx.x] = sh[0];
        __threadfence();
        int c = atomicAdd(&g_scan_ctr, 1);
        is_last = (c == gridDim.x - 1);
    }
    __syncthreads();
    if (!is_last) return;

    int v = (tid < SCAN_BLOCKS) ? __ldcg(&g_bsum[tid]) : 0;
    __syncthreads();
    sh[tid] = v;
    __syncthreads();
    for (int d = 1; d < 256; d <<= 1) {
        int x = (tid >= d) ? sh[tid - d] : 0;
        __syncthreads();
        sh[tid] += x;
        __syncthreads();
    }
    if (tid < SCAN_BLOCKS) g_bsum[tid] = sh[tid] - v;
    if (tid == 0) { g_off[N_NODES] = sh[255]; g_scan_ctr = 0; }
}

// ---------------------------------------------------------------------------
// Phase C: block-local exclusive scan + block prefix; offsets & cursors.
// TAIL: also echoes df into the output (coalesced DRAM STG, free here).
// ---------------------------------------------------------------------------
template <bool TAIL>
__global__ void scanC(const float* __restrict__ df, float* __restrict__ out)
{
    __shared__ int sh[256];
    int tid = threadIdx.x;
    int base = blockIdx.x * 1024 + tid * 4;
    int v[4];
    int s = 0;
    #pragma unroll
    for (int j = 0; j < 4; j++) {
        v[j] = (base + j < N_NODES) ? g_off[base + j] : 0;
        s += v[j];
    }
    sh[tid] = s;
    __syncthreads();
    for (int d = 1; d < 256; d <<= 1) {
        int x = (tid >= d) ? sh[tid - d] : 0;
        __syncthreads();
        sh[tid] += x;
        __syncthreads();
    }
    int ex = sh[tid] - s + g_bsum[blockIdx.x];
    #pragma unroll
    for (int j = 0; j < 4; j++) {
        if (base + j < N_NODES) {
            g_off[base + j]    = ex;
            g_cursor[base + j] = ex;
            if (TAIL)
                out[OUT_ELEMS + 3 * N_EDGES + base + j] = __ldg(df + base + j);
        }
        ex += v[j];
    }
}

// ---------------------------------------------------------------------------
// fill (x4 edges/thread, 4 atomics in flight). TAIL: also echoes sn/en/dfs
// as fully-coalesced float4 stores.
// ---------------------------------------------------------------------------
template <bool TAIL>
__global__ void fill_kernel(const int* __restrict__ sn, const int* __restrict__ en,
                            const float* __restrict__ dfs, float* __restrict__ out)
{
    int e0 = (blockIdx.x * blockDim.x + threadIdx.x) * 4;
    if (e0 >= N_EDGES) return;
    if (e0 + 4 <= N_EDGES) {
        int4   s4 = *(const int4*)(sn + e0);
        int4   d4 = *(const int4*)(en + e0);
        float4 f4 = *(const float4*)(dfs + e0);
        int p0 = atomicAdd(&g_cursor[d4.x], 1);
        int p1 = atomicAdd(&g_cursor[d4.y], 1);
        int p2 = atomicAdd(&g_cursor[d4.z], 1);
        int p3 = atomicAdd(&g_cursor[d4.w], 1);
        g_epay[p0] = make_float2(__int_as_float(s4.x), f4.x);
        g_epay[p1] = make_float2(__int_as_float(s4.y), f4.y);
        g_epay[p2] = make_float2(__int_as_float(s4.z), f4.z);
        g_epay[p3] = make_float2(__int_as_float(s4.w), f4.w);
        if (TAIL) {
            float* p = out + OUT_ELEMS;
            *(float4*)(p + e0) =
                make_float4((float)s4.x, (float)s4.y, (float)s4.z, (float)s4.w);
            *(float4*)(p + N_EDGES + e0) =
                make_float4((float)d4.x, (float)d4.y, (float)d4.z, (float)d4.w);
            *(float4*)(p + 2 * N_EDGES + e0) = f4;
        }
    } else {
        for (int e = e0; e < N_EDGES; e++) {
            int s = __ldg(sn + e), d = __ldg(en + e);
            float f = __ldg(dfs + e);
            int pos = atomicAdd(&g_cursor[d], 1);
            g_epay[pos] = make_float2(__int_as_float(s), f);
            if (TAIL) {
                float* p = out + OUT_ELEMS;
                p[e] = (float)s; p[N_EDGES + e] = (float)d; p[2 * N_EDGES + e] = f;
            }
        }
    }
}

// ---------------------------------------------------------------------------
// Gather pass: dst[n] = df[n] * sum_{e: end=n} src[start_e] * dfs_e
// 12 threads per node, one float4 chunk each, unrolled x4.
// ---------------------------------------------------------------------------
#define GB ((N_NODES * 12 + 255) / 256)     // 4688

__global__ void gather_pass(const float* __restrict__ src, float* __restrict__ dst,
                            const float* __restrict__ df)
{
    int t = blockIdx.x * blockDim.x + threadIdx.x;
    if (t >= N_NODES * 12) return;
    int n = t / 12;
    int q = t - n * 12;

    int o0 = __ldg(&g_off[n]);
    int o1 = __ldg(&g_off[n + 1]);

    float4 acc = make_float4(0.f, 0.f, 0.f, 0.f);
    int i = o0;
    for (; i + 4 <= o1; i += 4) {
        float2 p0 = __ldg(&g_epay[i]);
        float2 p1 = __ldg(&g_epay[i + 1]);
        float2 p2 = __ldg(&g_epay[i + 2]);
        float2 p3 = __ldg(&g_epay[i + 3]);
        float4 v0 = __ldg((const float4*)(src + (size_t)__float_as_int(p0.x) * DIN) + q);
        float4 v1 = __ldg((const float4*)(src + (size_t)__float_as_int(p1.x) * DIN) + q);
        float4 v2 = __ldg((const float4*)(src + (size_t)__float_as_int(p2.x) * DIN) + q);
        float4 v3 = __ldg((const float4*)(src + (size_t)__float_as_int(p3.x) * DIN) + q);
        acc.x = fmaf(v0.x, p0.y, acc.x); acc.y = fmaf(v0.y, p0.y, acc.y);
        acc.z = fmaf(v0.z, p0.y, acc.z); acc.w = fmaf(v0.w, p0.y, acc.w);
        acc.x = fmaf(v1.x, p1.y, acc.x); acc.y = fmaf(v1.y, p1.y, acc.y);
        acc.z = fmaf(v1.z, p1.y, acc.z); acc.w = fmaf(v1.w, p1.y, acc.w);
        acc.x = fmaf(v2.x, p2.y, acc.x); acc.y = fmaf(v2.y, p2.y, acc.y);
        acc.z = fmaf(v2.z, p2.y, acc.z); acc.w = fmaf(v2.w, p2.y, acc.w);
        acc.x = fmaf(v3.x, p3.y, acc.x); acc.y = fmaf(v3.y, p3.y, acc.y);
        acc.z = fmaf(v3.z, p3.y, acc.z); acc.w = fmaf(v3.w, p3.y, acc.w);
    }
    for (; i < o1; i++) {
        float2 p = __ldg(&g_epay[i]);
        float4 v = __ldg((const float4*)(src + (size_t)__float_as_int(p.x) * DIN) + q);
        acc.x = fmaf(v.x, p.y, acc.x); acc.y = fmaf(v.y, p.y, acc.y);
        acc.z = fmaf(v.z, p.y, acc.z); acc.w = fmaf(v.w, p.y, acc.w);
    }

    float f = __ldg(df + n);
    acc.x *= f; acc.y *= f; acc.z *= f; acc.w *= f;
    ((float4*)(dst + (size_t)n * DIN))[q] = acc;
}

// ---------------------------------------------------------------------------
// Persistent fused MLP on tensor cores (tf32 mma.sync, 3xTF32 compensation):
//   out = relu(x @ W1 + b1) @ W2 + b2
// ---------------------------------------------------------------------------
#define MLP_TM 128
#define MLP_THREADS 256
#define MLP_GRID 148
#define N_TILES ((N_NODES + MLP_TM - 1) / MLP_TM)      // 782
#define W_STRIDE 136
#define YT_STRIDE 52
#define MLP_SMEM_WORDS (48*W_STRIDE*2 + 128*W_STRIDE*2 + 256 + MLP_TM*YT_STRIDE)

__global__ void __launch_bounds__(MLP_THREADS, 1)
mlp_kernel(const float* __restrict__ x,
           const float* __restrict__ b1, const float* __restrict__ b2,
           float* __restrict__ out)
{
    extern __shared__ uint32_t smu[];
    uint32_t* W1hs = smu;                         // [48][136]
    uint32_t* W1ls = W1hs + 48 * W_STRIDE;
    uint32_t* W2hs = W1ls + 48 * W_STRIDE;        // [128][136]
    uint32_t* W2ls = W2hs + 128 * W_STRIDE;
    float*    b1s  = (float*)(W2ls + 128 * W_STRIDE);
    float*    b2s  = b1s + 128;
    float*    yt   = b2s + 128;                   // [128][52]

    int tid = threadIdx.x;

    for (int i = tid; i < 48 * 128; i += MLP_THREADS) {
        int k = i >> 7, n = i & 127;
        W1hs[k * W_STRIDE + n] = g_W1h[i];
        W1ls[k * W_STRIDE + n] = g_W1l[i];
    }
    for (int i = tid; i < 128 * 128; i += MLP_THREADS) {
        int k = i >> 7, n = i & 127;
        W2hs[k * W_STRIDE + n] = g_W2h[i];
        W2ls[k * W_STRIDE + n] = g_W2l[i];
    }
    if (tid < 128) { b1s[tid] = __ldg(b1 + tid); b2s[tid] = __ldg(b2 + tid); }

    int warp = tid >> 5;
    int lane = tid & 31;
    int r = lane >> 2;
    int c = lane & 3;
    int srcA = (lane & ~3) | (c >> 1);
    int srcB = srcA + 2;
    bool odd = (c & 1);

    for (int tile = blockIdx.x; tile < N_TILES; tile += MLP_GRID) {
        int node0 = tile * MLP_TM;

        __syncthreads();
        for (int i = tid; i < MLP_TM * 48; i += MLP_THREADS) {
            int rr = i / 48;
            int n = node0 + rr;
            yt[rr * YT_STRIDE + (i - rr * 48)] =
                (n < N_NODES) ? __ldg(x + (size_t)n * 48 + (i - rr * 48)) : 0.f;
        }
        __syncthreads();

        float d[16][4];
        float h[16][4];

        // ---- stage 1: H = relu(Y @ W1 + b1), K = 48 ----
        #pragma unroll
        for (int nt = 0; nt < 16; nt++) {
            d[nt][0] = b1s[nt * 8 + 2 * c];
            d[nt][1] = b1s[nt * 8 + 2 * c + 1];
            d[nt][2] = d[nt][0];
            d[nt][3] = d[nt][1];
        }
        {
            const float* yb = yt + warp * 16 * YT_STRIDE;
            #pragma unroll
            for (int ks = 0; ks < 6; ks++) {
                int k0 = ks * 8;
                uint32_t ah[4], al[4];
                split_tf32(yb[r * YT_STRIDE + k0 + c],           ah[0], al[0]);
                split_tf32(yb[(r + 8) * YT_STRIDE + k0 + c],     ah[1], al[1]);
                split_tf32(yb[r * YT_STRIDE + k0 + c + 4],       ah[2], al[2]);
                split_tf32(yb[(r + 8) * YT_STRIDE + k0 + c + 4], ah[3], al[3]);
                #pragma unroll
                for (int nt = 0; nt < 16; nt++) {
                    uint32_t bh0 = W1hs[(k0 + c) * W_STRIDE + nt * 8 + r];
                    uint32_t bh1 = W1hs[(k0 + c + 4) * W_STRIDE + nt * 8 + r];
                    uint32_t bl0 = W1ls[(k0 + c) * W_STRIDE + nt * 8 + r];
                    uint32_t bl1 = W1ls[(k0 + c + 4) * W_STRIDE + nt * 8 + r];
                    mma_tf32(d[nt], ah[0], ah[1], ah[2], ah[3], bh0, bh1);
                    mma_tf32(d[nt], al[0], al[1], al[2], al[3], bh0, bh1);
                    mma_tf32(d[nt], ah[0], ah[1], ah[2], ah[3], bl0, bl1);
                }
            }
        }
        #pragma unroll
        for (int nt = 0; nt < 16; nt++) {
            h[nt][0] = fmaxf(d[nt][0], 0.f);
            h[nt][1] = fmaxf(d[nt][1], 0.f);
            h[nt][2] = fmaxf(d[nt][2], 0.f);
            h[nt][3] = fmaxf(d[nt][3], 0.f);
        }

        // ---- stage 2: OUT = H @ W2 + b2, K = 128 ----
        #pragma unroll
        for (int nt = 0; nt < 16; nt++) {
            d[nt][0] = b2s[nt * 8 + 2 * c];
            d[nt][1] = b2s[nt * 8 + 2 * c + 1];
            d[nt][2] = d[nt][0];
            d[nt][3] = d[nt][1];
        }
        #pragma unroll
        for (int ks = 0; ks < 16; ks++) {
            int k0 = ks * 8;
            float w0 = __shfl_sync(0xFFFFFFFFu, h[ks][0], srcA);
            float w1 = __shfl_sync(0xFFFFFFFFu, h[ks][1], srcA);
            float w2 = __shfl_sync(0xFFFFFFFFu, h[ks][2], srcA);
            float w3 = __shfl_sync(0xFFFFFFFFu, h[ks][3], srcA);
            float x0 = __shfl_sync(0xFFFFFFFFu, h[ks][0], srcB);
            float x1 = __shfl_sync(0xFFFFFFFFu, h[ks][1], srcB);
            float x2 = __shfl_sync(0xFFFFFFFFu, h[ks][2], srcB);
            float x3 = __shfl_sync(0xFFFFFFFFu, h[ks][3], srcB);
            uint32_t ah[4], al[4];
            split_tf32(odd ? w1 : w0, ah[0], al[0]);
            split_tf32(odd ? w3 : w2, ah[1], al[1]);
            split_tf32(odd ? x1 : x0, ah[2], al[2]);
            split_tf32(odd ? x3 : x2, ah[3], al[3]);
            #pragma unroll
            for (int nt = 0; nt < 16; nt++) {
                uint32_t bh0 = W2hs[(k0 + c) * W_STRIDE + nt * 8 + r];
                uint32_t bh1 = W2hs[(k0 + c + 4) * W_STRIDE + nt * 8 + r];
                uint32_t bl0 = W2ls[(k0 + c) * W_STRIDE + nt * 8 + r];
                uint32_t bl1 = W2ls[(k0 + c + 4) * W_STRIDE + nt * 8 + r];
                mma_tf32(d[nt], ah[0], ah[1], ah[2], ah[3], bh0, bh1);
                mma_tf32(d[nt], al[0], al[1], al[2], al[3], bh0, bh1);
                mma_tf32(d[nt], ah[0], ah[1], ah[2], ah[3], bl0, bl1);
            }
        }
        {
            int row0 = node0 + warp * 16 + r;
            int row1 = row0 + 8;
            #pragma unroll
            for (int nt = 0; nt < 16; nt++) {
                if (row0 < N_NODES)
                    *(float2*)(out + (size_t)row0 * 128 + nt * 8 + 2 * c) =
                        make_float2(d[nt][0], d[nt][1]);
                if (row1 < N_NODES)
                    *(float2*)(out + (size_t)row1 * 128 + nt * 8 + 2 * c) =
                        make_float2(d[nt][2], d[nt][3]);
            }
        }
    }
}

extern "C" void kernel_launch(void* const* d_in, const int* in_sizes, int n_in,
                              void* d_out, int out_size)
{
    const float* y   = (const float*)d_in[0];
    const int*   sn  = (const int*)  d_in[1];
    const int*   en  = (const int*)  d_in[2];
    const float* dfs = (const float*)d_in[3];
    const float* df  = (const float*)d_in[4];
    const float* W1  = (const float*)d_in[5];
    const float* b1  = (const float*)d_in[6];
    const float* W2  = (const float*)d_in[7];
    const float* b2  = (const float*)d_in[8];
    float* out = (float*)d_out;

    float *bufA, *bufB;
    cudaGetSymbolAddress((void**)&bufA, g_bufA);
    cudaGetSymbolAddress((void**)&bufB, g_bufB);
    int* offp;
    cudaGetSymbolAddress((void**)&offp, g_off);

    cudaFuncSetAttribute(mlp_kernel, cudaFuncAttributeMaxDynamicSharedMemorySize,
                         MLP_SMEM_WORDS * (int)sizeof(uint32_t));

    const bool tail = (out_size >= FULL_OUT);

    // ---- CSR build (by destination), weight split + echoes overlapped ----
    cudaMemsetAsync(offp, 0, N_NODES * sizeof(int));
    hist_and_split<<<HB + WB, 256>>>(en, W1, W2);
    scanAB<<<SCAN_BLOCKS, 256>>>();
    if (tail) {
        scanC<true><<<SCAN_BLOCKS, 256>>>(df, out);
        fill_kernel<true><<<HB, 256>>>(sn, en, dfs, out);
    } else {
        scanC<false><<<SCAN_BLOCKS, 256>>>(df, out);
        fill_kernel<false><<<HB, 256>>>(sn, en, dfs, out);
    }

    // ---- two gather passes ----
    gather_pass<<<GB, 256>>>(y,    bufA, df);
    gather_pass<<<GB, 256>>>(bufA, bufB, df);

    // ---- persistent fused tensor-core MLP ----
    mlp_kernel<<<MLP_GRID, MLP_THREADS,
                 MLP_SMEM_WORDS * sizeof(uint32_t)>>>(bufB, b1, b2, out);
}